// round 1
// baseline (speedup 1.0000x reference)
#include <cuda_runtime.h>
#include <math.h>

#define NU 100000
#define NN 20000
#define NT 120000
#define CC 128
#define EE 250000
#define NLAYER 2

// ---------------- scratch (device globals; no allocations allowed) ----------
__device__ float g_x0[NT * CC];
__device__ float g_x1[NT * CC];
__device__ float g_q[NT * CC];
__device__ float g_krel[(NU + NN + NU) * CC];
__device__ float g_vrel[(NU + NN + NU) * CC];
__device__ float g_exb[3 * EE * 4];
__device__ float g_den[3 * NU * 4];
__device__ float g_agg[NT * CC];
__device__ float g_Weff[12 * CC * CC];
__device__ float g_beff[12 * CC];

__device__ __forceinline__ float gelu_exact(float x) {
    return 0.5f * x * (1.0f + erff(x * 0.70710678118654752f));
}

// ---------------- effective relation weights -------------------------------
// Wk_eff[:, h*32+e] = sum_d Wk[:, h*32+d] * a_rel[h,d,e]   (same for v with m_rel)
// blockIdx.x encodes (layer, relation, k-or-v): 12 blocks total.
__global__ void build_eff_kernel(const float* __restrict__ Wk, const float* __restrict__ bk,
                                 const float* __restrict__ Wv, const float* __restrict__ bv,
                                 const float* __restrict__ a_rel, const float* __restrict__ m_rel,
                                 float* __restrict__ Weff, float* __restrict__ beff) {
    int b = blockIdx.x;
    int l = b / 6, rem = b % 6, r = rem >> 1, kv = rem & 1;
    int st = (r == 1) ? 1 : 0;  // src type: rel0=user, rel1=news, rel2=user
    const float* W   = (kv ? Wv : Wk) + (l * 2 + st) * CC * CC;
    const float* bi  = (kv ? bv : bk) + (l * 2 + st) * CC;
    const float* rel = (kv ? m_rel : a_rel) + (l * 3 + r) * 4096;  // [H=4][32][32]
    float* out  = Weff + ((l * 3 + r) * 2 + kv) * CC * CC;
    float* bout = beff + ((l * 3 + r) * 2 + kv) * CC;

    __shared__ float rs[4096];
    for (int i = threadIdx.x; i < 4096; i += blockDim.x) rs[i] = rel[i];
    __syncthreads();

    for (int idx = threadIdx.x; idx < CC * CC; idx += blockDim.x) {
        int i = idx >> 7, j = idx & 127, h = j >> 5, e = j & 31;
        float s = 0.f;
#pragma unroll
        for (int d = 0; d < 32; d++)
            s += W[i * CC + h * 32 + d] * rs[h * 1024 + d * 32 + e];
        out[idx] = s;
    }
    if (threadIdx.x < CC) {
        int j = threadIdx.x, h = j >> 5, e = j & 31;
        float s = 0.f;
#pragma unroll
        for (int d = 0; d < 32; d++)
            s += bi[h * 32 + d] * rs[h * 1024 + d * 32 + e];
        bout[j] = s;
    }
}

// ---------------- GEMM: Y[N,128] = act(X[N,128]) @ W[128,128] + b ----------
// mode 0: plain. mode 1: gelu on X, epilogue sigmoid-skip blend with xold + relu.
// Tile: 64 rows x 128 cols per block of 256 threads; X tile + full W in smem.
__global__ void gemm128_kernel(const float* __restrict__ X, const float* __restrict__ W,
                               const float* __restrict__ bias, float* __restrict__ Y,
                               int N, int mode, const float* __restrict__ xold,
                               const float* __restrict__ skipPtr) {
    extern __shared__ float sm[];
    float4* Xs4 = (float4*)sm;               // 64*32 float4 = 32 KB
    float4* Ws4 = (float4*)(sm + 64 * CC);   // 128*32 float4 = 64 KB
    int tid = threadIdx.x;
    int row0 = blockIdx.x * 64;

    const float4* W4 = (const float4*)W;
#pragma unroll
    for (int i = 0; i < 16; i++) Ws4[tid + i * 256] = W4[tid + i * 256];

    const float4* X4 = (const float4*)X;
#pragma unroll
    for (int i = 0; i < 8; i++) {
        int f4 = tid + i * 256;           // 0..2047
        int r = f4 >> 5;
        int gr = row0 + r;
        float4 v = make_float4(0.f, 0.f, 0.f, 0.f);
        if (gr < N) {
            v = X4[gr * 32 + (f4 & 31)];
            if (mode == 1) {
                v.x = gelu_exact(v.x); v.y = gelu_exact(v.y);
                v.z = gelu_exact(v.z); v.w = gelu_exact(v.w);
            }
        }
        Xs4[f4] = v;
    }
    __syncthreads();

    int tx = tid & 31, ty = tid >> 5;
    float acc[8][4];
#pragma unroll
    for (int i = 0; i < 8; i++)
#pragma unroll
        for (int c = 0; c < 4; c++) acc[i][c] = 0.f;

#pragma unroll 4
    for (int k0 = 0; k0 < CC; k0 += 4) {
        float4 w0 = Ws4[(k0 + 0) * 32 + tx];
        float4 w1 = Ws4[(k0 + 1) * 32 + tx];
        float4 w2 = Ws4[(k0 + 2) * 32 + tx];
        float4 w3 = Ws4[(k0 + 3) * 32 + tx];
#pragma unroll
        for (int i = 0; i < 8; i++) {
            float4 xv = Xs4[(ty * 8 + i) * 32 + (k0 >> 2)];
            acc[i][0] = fmaf(xv.x, w0.x, fmaf(xv.y, w1.x, fmaf(xv.z, w2.x, fmaf(xv.w, w3.x, acc[i][0]))));
            acc[i][1] = fmaf(xv.x, w0.y, fmaf(xv.y, w1.y, fmaf(xv.z, w2.y, fmaf(xv.w, w3.y, acc[i][1]))));
            acc[i][2] = fmaf(xv.x, w0.z, fmaf(xv.y, w1.z, fmaf(xv.z, w2.z, fmaf(xv.w, w3.z, acc[i][2]))));
            acc[i][3] = fmaf(xv.x, w0.w, fmaf(xv.y, w1.w, fmaf(xv.z, w2.w, fmaf(xv.w, w3.w, acc[i][3]))));
        }
    }

    float4 bj = ((const float4*)bias)[tx];
    float aS = 0.f, bS = 0.f;
    if (mode == 1) {
        float s = *skipPtr;
        aS = 1.f / (1.f + expf(-s));
        bS = 1.f - aS;
    }
#pragma unroll
    for (int i = 0; i < 8; i++) {
        int gr = row0 + ty * 8 + i;
        if (gr >= N) continue;
        float4 o;
        o.x = acc[i][0] + bj.x; o.y = acc[i][1] + bj.y;
        o.z = acc[i][2] + bj.z; o.w = acc[i][3] + bj.w;
        if (mode == 1) {
            float4 xo = ((const float4*)xold)[gr * 32 + tx];
            o.x = fmaxf(fmaf(aS, o.x, bS * xo.x), 0.f);
            o.y = fmaxf(fmaf(aS, o.y, bS * xo.y), 0.f);
            o.z = fmaxf(fmaf(aS, o.z, bS * xo.z), 0.f);
            o.w = fmaxf(fmaf(aS, o.w, bS * xo.w), 0.f);
        }
        ((float4*)Y)[gr * 32 + tx] = o;
    }
}

// ---------------- edge pass A: score -> exp -> den atomicAdd ----------------
// One warp per edge. lane covers dims [4*lane, 4*lane+4); head = lane>>3.
// Softmax shift is omitted (scores are O(1)-scaled, exp safe; ratio invariant).
__global__ void edge_score_kernel(const int* __restrict__ ei, const float* __restrict__ q,
                                  const float* __restrict__ krel, const float* __restrict__ prel,
                                  float* __restrict__ den, float* __restrict__ exb) {
    int w = (blockIdx.x * blockDim.x + threadIdx.x) >> 5;
    int lane = threadIdx.x & 31;
    if (w >= EE) return;
    int src = ei[w];
    int dst = ei[EE + w];
    float4 qv = ((const float4*)q)[dst * 32 + lane];
    float4 kv = ((const float4*)krel)[src * 32 + lane];
    float s = qv.x * kv.x + qv.y * kv.y + qv.z * kv.z + qv.w * kv.w;
    s += __shfl_xor_sync(0xffffffffu, s, 1);
    s += __shfl_xor_sync(0xffffffffu, s, 2);
    s += __shfl_xor_sync(0xffffffffu, s, 4);
    if ((lane & 7) == 0) {
        int h = lane >> 3;
        float sc = s * prel[h] * 0.17677669529663689f;  // 1/sqrt(32)
        float ex = expf(sc);
        exb[w * 4 + h] = ex;
        atomicAdd(&den[dst * 4 + h], ex);
    }
}

// ---------------- edge pass B: alpha-weighted scatter into agg --------------
__global__ void edge_agg_kernel(const int* __restrict__ ei, const float* __restrict__ vrel,
                                const float* __restrict__ den, const float* __restrict__ exb,
                                float* __restrict__ agg) {
    int w = (blockIdx.x * blockDim.x + threadIdx.x) >> 5;
    int lane = threadIdx.x & 31;
    if (w >= EE) return;
    int src = ei[w];
    int dst = ei[EE + w];
    int h = lane >> 3;
    float alpha = exb[w * 4 + h] / (den[dst * 4 + h] + 1e-16f);
    float4 v = ((const float4*)vrel)[src * 32 + lane];
    v.x *= alpha; v.y *= alpha; v.z *= alpha; v.w *= alpha;
    float* p = &agg[dst * CC + lane * 4];
    asm volatile("red.global.add.v4.f32 [%0], {%1, %2, %3, %4};"
                 :: "l"(p), "f"(v.x), "f"(v.y), "f"(v.z), "f"(v.w)
                 : "memory");
}

// ---------------- host orchestration ----------------------------------------
extern "C" void kernel_launch(void* const* d_in, const int* in_sizes, int n_in,
                              void* d_out, int out_size) {
    const float* x_user = (const float*)d_in[0];
    const float* x_news = (const float*)d_in[1];
    const int* eis[3] = {(const int*)d_in[2], (const int*)d_in[3], (const int*)d_in[4]};
    const float* Wk = (const float*)d_in[5];
    const float* bk = (const float*)d_in[6];
    const float* Wq = (const float*)d_in[7];
    const float* bq = (const float*)d_in[8];
    const float* Wv = (const float*)d_in[9];
    const float* bv = (const float*)d_in[10];
    const float* Wa = (const float*)d_in[11];
    const float* ba = (const float*)d_in[12];
    const float* skip = (const float*)d_in[13];
    const float* a_rel = (const float*)d_in[14];
    const float* m_rel = (const float*)d_in[15];
    const float* p_rel = (const float*)d_in[16];

    float *x0, *x1, *q, *krel, *vrel, *exb, *den, *agg, *Weff, *beff;
    cudaGetSymbolAddress((void**)&x0, g_x0);
    cudaGetSymbolAddress((void**)&x1, g_x1);
    cudaGetSymbolAddress((void**)&q, g_q);
    cudaGetSymbolAddress((void**)&krel, g_krel);
    cudaGetSymbolAddress((void**)&vrel, g_vrel);
    cudaGetSymbolAddress((void**)&exb, g_exb);
    cudaGetSymbolAddress((void**)&den, g_den);
    cudaGetSymbolAddress((void**)&agg, g_agg);
    cudaGetSymbolAddress((void**)&Weff, g_Weff);
    cudaGetSymbolAddress((void**)&beff, g_beff);

    const int smemGemm = (64 * CC + CC * CC) * (int)sizeof(float);  // 96 KB
    cudaFuncSetAttribute(gemm128_kernel, cudaFuncAttributeMaxDynamicSharedMemorySize, smemGemm);

    static const int relSrc[3]  = {0, 1, 0};
    static const int relDst[3]  = {1, 0, 0};
    static const int relRows[3] = {NU, NN, NU};
    static const int relOff[3]  = {0, NU, NU + NN};

    // inputs -> x0 (user then news, packed)
    cudaMemcpyAsync(x0, x_user, (size_t)NU * CC * 4, cudaMemcpyDeviceToDevice, 0);
    cudaMemcpyAsync(x0 + (size_t)NU * CC, x_news, (size_t)NN * CC * 4, cudaMemcpyDeviceToDevice, 0);

    // effective relation-fused projection weights (all layers/relations)
    build_eff_kernel<<<12, 256, 0, 0>>>(Wk, bk, Wv, bv, a_rel, m_rel, Weff, beff);

    const int edgeBlocks = (EE + 7) / 8;  // warp per edge, 8 warps/block

    for (int l = 0; l < NLAYER; l++) {
        float* xin  = (l == 0) ? x0 : x1;
        float* xout = (l == 0) ? x1 : x0;

        // q projections per type
        gemm128_kernel<<<(NU + 63) / 64, 256, smemGemm, 0>>>(
            xin, Wq + (size_t)(l * 2 + 0) * CC * CC, bq + (l * 2 + 0) * CC,
            q, NU, 0, nullptr, nullptr);
        gemm128_kernel<<<(NN + 63) / 64, 256, smemGemm, 0>>>(
            xin + (size_t)NU * CC, Wq + (size_t)(l * 2 + 1) * CC * CC, bq + (l * 2 + 1) * CC,
            q + (size_t)NU * CC, NN, 0, nullptr, nullptr);

        // k_rel / v_rel projections per relation (fused with a_rel/m_rel)
        for (int r = 0; r < 3; r++) {
            int st = relSrc[r];
            const float* xs_ = (st == 0) ? xin : xin + (size_t)NU * CC;
            int rows = relRows[r];
            size_t widx = (size_t)((l * 3 + r) * 2) * CC * CC;
            size_t bidx = (size_t)((l * 3 + r) * 2) * CC;
            gemm128_kernel<<<(rows + 63) / 64, 256, smemGemm, 0>>>(
                xs_, Weff + widx, beff + bidx,
                krel + (size_t)relOff[r] * CC, rows, 0, nullptr, nullptr);
            gemm128_kernel<<<(rows + 63) / 64, 256, smemGemm, 0>>>(
                xs_, Weff + widx + CC * CC, beff + bidx + CC,
                vrel + (size_t)relOff[r] * CC, rows, 0, nullptr, nullptr);
        }

        cudaMemsetAsync(agg, 0, (size_t)NT * CC * 4, 0);
        cudaMemsetAsync(den, 0, (size_t)3 * NU * 4 * 4, 0);

        for (int r = 0; r < 3; r++) {
            int dt = relDst[r];
            const float* qd = q + (size_t)((dt == 0) ? 0 : NU) * CC;
            float* aggd = agg + (size_t)((dt == 0) ? 0 : NU) * CC;
            edge_score_kernel<<<edgeBlocks, 256, 0, 0>>>(
                eis[r], qd, krel + (size_t)relOff[r] * CC,
                p_rel + (l * 3 + r) * 4, den + (size_t)r * NU * 4, exb + (size_t)r * EE * 4);
            edge_agg_kernel<<<edgeBlocks, 256, 0, 0>>>(
                eis[r], vrel + (size_t)relOff[r] * CC,
                den + (size_t)r * NU * 4, exb + (size_t)r * EE * 4, aggd);
        }

        // output projection + skip blend + relu, per type
        gemm128_kernel<<<(NU + 63) / 64, 256, smemGemm, 0>>>(
            agg, Wa + (size_t)(l * 2 + 0) * CC * CC, ba + (l * 2 + 0) * CC,
            xout, NU, 1, xin, skip + l * 2 + 0);
        gemm128_kernel<<<(NN + 63) / 64, 256, smemGemm, 0>>>(
            agg + (size_t)NU * CC, Wa + (size_t)(l * 2 + 1) * CC * CC, ba + (l * 2 + 1) * CC,
            xout + (size_t)NU * CC, NN, 1, xin + (size_t)NU * CC, skip + l * 2 + 1);
    }

    // after 2 layers result lives in x0; output layout = concat(user, news)
    cudaMemcpyAsync(d_out, x0, (size_t)NT * CC * 4, cudaMemcpyDeviceToDevice, 0);
}

// round 3
// speedup vs baseline: 1.2409x; 1.2409x over previous
#include <cuda_runtime.h>
#include <math.h>
#include <stdint.h>

#define NU 100000
#define NN 20000
#define NT 120000
#define CC 128
#define EE 250000
#define NLAYER 2

// ---------------- scratch (device globals; no allocations allowed) ----------
__device__ float g_x0[NT * CC];
__device__ float g_x1[NT * CC];
__device__ float g_q[NT * CC];
__device__ float g_krel[(NU + NN + NU) * CC];
__device__ float g_vrel[(NU + NN + NU) * CC];
__device__ float g_exb[3 * EE * 4];
__device__ float g_den[3 * NU * 4];
__device__ float g_agg[NT * CC];
__device__ float g_Weff[12 * CC * CC];
__device__ float g_beff[12 * CC];
__device__ float g_Wt[20 * CC * CC];   // tf32-rounded, transposed [n][k] weights

__device__ __forceinline__ float gelu_exact(float x) {
    return 0.5f * x * (1.0f + erff(x * 0.70710678118654752f));
}
__device__ __forceinline__ uint32_t cvt_tf32(float f) {
    uint32_t u;
    asm("cvt.rna.tf32.f32 %0, %1;" : "=r"(u) : "f"(f));
    return u;
}

// ---------------- effective relation weights -------------------------------
// Wk_eff[:, h*32+e] = sum_d Wk[:, h*32+d] * a_rel[h,d,e]  (v uses m_rel)
__global__ void build_eff_kernel(const float* __restrict__ Wk, const float* __restrict__ bk,
                                 const float* __restrict__ Wv, const float* __restrict__ bv,
                                 const float* __restrict__ a_rel, const float* __restrict__ m_rel,
                                 float* __restrict__ Weff, float* __restrict__ beff) {
    int b = blockIdx.x;
    int l = b / 6, rem = b % 6, r = rem >> 1, kv = rem & 1;
    int st = (r == 1) ? 1 : 0;
    const float* W   = (kv ? Wv : Wk) + (l * 2 + st) * CC * CC;
    const float* bi  = (kv ? bv : bk) + (l * 2 + st) * CC;
    const float* rel = (kv ? m_rel : a_rel) + (l * 3 + r) * 4096;
    float* out  = Weff + ((l * 3 + r) * 2 + kv) * CC * CC;
    float* bout = beff + ((l * 3 + r) * 2 + kv) * CC;

    __shared__ float rs[4096];
    for (int i = threadIdx.x; i < 4096; i += blockDim.x) rs[i] = rel[i];
    __syncthreads();

    for (int idx = threadIdx.x; idx < CC * CC; idx += blockDim.x) {
        int i = idx >> 7, j = idx & 127, h = j >> 5, e = j & 31;
        float s = 0.f;
#pragma unroll
        for (int d = 0; d < 32; d++)
            s += W[i * CC + h * 32 + d] * rs[h * 1024 + d * 32 + e];
        out[idx] = s;
    }
    if (threadIdx.x < CC) {
        int j = threadIdx.x, h = j >> 5, e = j & 31;
        float s = 0.f;
#pragma unroll
        for (int d = 0; d < 32; d++)
            s += bi[h * 32 + d] * rs[h * 1024 + d * 32 + e];
        bout[j] = s;
    }
}

// ---------------- weight prep: transpose + tf32 round ----------------------
// 20 matrices per layout: l*10 + {0,1}=Wq u/n, {2..7}=Weff k/v per rel, {8,9}=Wa u/n
__global__ void prep_wt_kernel(const float* __restrict__ Wq, const float* __restrict__ Wa,
                               const float* __restrict__ Weff, float* __restrict__ Wt) {
    int b = blockIdx.x;
    int l = b / 10, m = b % 10;
    const float* src;
    if (m < 2)       src = Wq + (size_t)(l * 2 + m) * CC * CC;
    else if (m < 8)  src = Weff + (size_t)((l * 3 + (m - 2) / 2) * 2 + ((m - 2) & 1)) * CC * CC;
    else             src = Wa + (size_t)(l * 2 + (m - 8)) * CC * CC;
    float* out = Wt + (size_t)b * CC * CC;
    for (int idx = threadIdx.x; idx < CC * CC; idx += blockDim.x) {
        int n = idx >> 7, k = idx & 127;
        ((uint32_t*)out)[idx] = cvt_tf32(src[k * CC + n]);  // out[n][k] = W[k][n]
    }
}

// ---------------- tensor-core GEMM via mma.sync tf32 -------------------------
// Y[N,128] = act(X[N,128]) @ W[128,128] + b
// mode 0: plain+bias. mode 1: gelu on X, epilogue sigmoid-skip blend + relu.
// 256 thr = 8 warps as 4(M)x2(N); warp tile 32x64 of m16n8k8 frags.
#define ASTRIDE 132
__global__ __launch_bounds__(256, 1)
void tc_gemm_kernel(const float* __restrict__ X, const float* __restrict__ Wt,
                    const float* __restrict__ bias, float* __restrict__ Y,
                    int N, int mode, const float* __restrict__ xold,
                    const float* __restrict__ skipPtr) {
    extern __shared__ float sm[];
    float* As = sm;                    // [128][132]
    float* Bs = sm + 128 * ASTRIDE;    // [128][132]
    int tid = threadIdx.x;
    int row0 = blockIdx.x * 128;

    // stage A (gelu if mode1, tf32 round), float4 per thread per iter
    const float4* X4 = (const float4*)X;
#pragma unroll
    for (int it = 0; it < 16; it++) {
        int idx = tid + it * 256;          // 0..4095 float4s
        int row = idx >> 5, q = idx & 31;
        int gr = row0 + row;
        float4 v = make_float4(0.f, 0.f, 0.f, 0.f);
        if (gr < N) {
            v = X4[gr * 32 + q];
            if (mode == 1) {
                v.x = gelu_exact(v.x); v.y = gelu_exact(v.y);
                v.z = gelu_exact(v.z); v.w = gelu_exact(v.w);
            }
        }
        uint4 u;
        u.x = cvt_tf32(v.x); u.y = cvt_tf32(v.y); u.z = cvt_tf32(v.z); u.w = cvt_tf32(v.w);
        *(uint4*)&As[row * ASTRIDE + q * 4] = u;
    }
    // stage B (pre-rounded, [n][k])
    const uint4* W4 = (const uint4*)Wt;
#pragma unroll
    for (int it = 0; it < 16; it++) {
        int idx = tid + it * 256;
        int row = idx >> 5, q = idx & 31;
        *(uint4*)&Bs[row * ASTRIDE + q * 4] = W4[idx];
    }
    __syncthreads();

    int wid = tid >> 5, lane = tid & 31;
    int wm = wid & 3, wn = wid >> 2;       // warp tile origin (wm*32, wn*64)
    int g = lane >> 2, t = lane & 3;

    float acc[16][4];
#pragma unroll
    for (int i = 0; i < 16; i++)
#pragma unroll
        for (int c = 0; c < 4; c++) acc[i][c] = 0.f;

#pragma unroll
    for (int k0 = 0; k0 < CC; k0 += 8) {
        uint32_t a[2][4];
#pragma unroll
        for (int m = 0; m < 2; m++) {
            int r0 = wm * 32 + m * 16 + g;
            const uint32_t* Ai = (const uint32_t*)As;
            a[m][0] = Ai[r0 * ASTRIDE + k0 + t];
            a[m][1] = Ai[(r0 + 8) * ASTRIDE + k0 + t];
            a[m][2] = Ai[r0 * ASTRIDE + k0 + t + 4];
            a[m][3] = Ai[(r0 + 8) * ASTRIDE + k0 + t + 4];
        }
        uint32_t b[8][2];
#pragma unroll
        for (int n = 0; n < 8; n++) {
            int c0 = wn * 64 + n * 8 + g;
            const uint32_t* Bi = (const uint32_t*)Bs;
            b[n][0] = Bi[c0 * ASTRIDE + k0 + t];
            b[n][1] = Bi[c0 * ASTRIDE + k0 + t + 4];
        }
#pragma unroll
        for (int m = 0; m < 2; m++)
#pragma unroll
            for (int n = 0; n < 8; n++) {
                float* c = acc[m * 8 + n];
                asm volatile(
                    "mma.sync.aligned.m16n8k8.row.col.f32.tf32.tf32.f32 "
                    "{%0,%1,%2,%3}, {%4,%5,%6,%7}, {%8,%9}, {%0,%1,%2,%3};"
                    : "+f"(c[0]), "+f"(c[1]), "+f"(c[2]), "+f"(c[3])
                    : "r"(a[m][0]), "r"(a[m][1]), "r"(a[m][2]), "r"(a[m][3]),
                      "r"(b[n][0]), "r"(b[n][1]));
            }
    }

    // epilogue
    float aS = 1.f, bS = 0.f;
    if (mode == 1) {
        float s = *skipPtr;
        aS = 1.f / (1.f + expf(-s));
        bS = 1.f - aS;
    }
#pragma unroll
    for (int m = 0; m < 2; m++) {
#pragma unroll
        for (int h = 0; h < 2; h++) {
            int gr = row0 + wm * 32 + m * 16 + h * 8 + g;
            if (gr >= N) continue;
#pragma unroll
            for (int n = 0; n < 8; n++) {
                int col = wn * 64 + n * 8 + 2 * t;
                float2 o;
                o.x = acc[m * 8 + n][2 * h + 0] + bias[col];
                o.y = acc[m * 8 + n][2 * h + 1] + bias[col + 1];
                if (mode == 1) {
                    float2 xo = *(const float2*)&xold[gr * CC + col];
                    o.x = fmaxf(fmaf(aS, o.x, bS * xo.x), 0.f);
                    o.y = fmaxf(fmaf(aS, o.y, bS * xo.y), 0.f);
                }
                *(float2*)&Y[gr * CC + col] = o;
            }
        }
    }
}

// ---------------- edge pass A: score -> exp -> den atomicAdd ----------------
__global__ void edge_score_kernel(const int* __restrict__ ei, const float* __restrict__ q,
                                  const float* __restrict__ krel, const float* __restrict__ prel,
                                  float* __restrict__ den, float* __restrict__ exb) {
    int w = (blockIdx.x * blockDim.x + threadIdx.x) >> 5;
    int lane = threadIdx.x & 31;
    if (w >= EE) return;
    int src = ei[w];
    int dst = ei[EE + w];
    float4 qv = ((const float4*)q)[dst * 32 + lane];
    float4 kv = ((const float4*)krel)[src * 32 + lane];
    float s = qv.x * kv.x + qv.y * kv.y + qv.z * kv.z + qv.w * kv.w;
    s += __shfl_xor_sync(0xffffffffu, s, 1);
    s += __shfl_xor_sync(0xffffffffu, s, 2);
    s += __shfl_xor_sync(0xffffffffu, s, 4);
    if ((lane & 7) == 0) {
        int h = lane >> 3;
        float sc = s * prel[h] * 0.17677669529663689f;
        float ex = expf(sc);
        exb[w * 4 + h] = ex;
        atomicAdd(&den[dst * 4 + h], ex);
    }
}

// ---------------- edge pass B: alpha-weighted scatter into agg --------------
__global__ void edge_agg_kernel(const int* __restrict__ ei, const float* __restrict__ vrel,
                                const float* __restrict__ den, const float* __restrict__ exb,
                                float* __restrict__ agg) {
    int w = (blockIdx.x * blockDim.x + threadIdx.x) >> 5;
    int lane = threadIdx.x & 31;
    if (w >= EE) return;
    int src = ei[w];
    int dst = ei[EE + w];
    int h = lane >> 3;
    float alpha = exb[w * 4 + h] / (den[dst * 4 + h] + 1e-16f);
    float4 v = ((const float4*)vrel)[src * 32 + lane];
    v.x *= alpha; v.y *= alpha; v.z *= alpha; v.w *= alpha;
    float* p = &agg[dst * CC + lane * 4];
    asm volatile("red.global.add.v4.f32 [%0], {%1, %2, %3, %4};"
                 :: "l"(p), "f"(v.x), "f"(v.y), "f"(v.z), "f"(v.w)
                 : "memory");
}

// ---------------- host orchestration ----------------------------------------
extern "C" void kernel_launch(void* const* d_in, const int* in_sizes, int n_in,
                              void* d_out, int out_size) {
    const float* x_user = (const float*)d_in[0];
    const float* x_news = (const float*)d_in[1];
    const int* eis[3] = {(const int*)d_in[2], (const int*)d_in[3], (const int*)d_in[4]};
    const float* Wk = (const float*)d_in[5];
    const float* bk = (const float*)d_in[6];
    const float* Wq = (const float*)d_in[7];
    const float* bq = (const float*)d_in[8];
    const float* Wv = (const float*)d_in[9];
    const float* bv = (const float*)d_in[10];
    const float* Wa = (const float*)d_in[11];
    const float* ba = (const float*)d_in[12];
    const float* skip = (const float*)d_in[13];
    const float* a_rel = (const float*)d_in[14];
    const float* m_rel = (const float*)d_in[15];
    const float* p_rel = (const float*)d_in[16];

    float *x0, *x1, *q, *krel, *vrel, *exb, *den, *agg, *Weff, *beff, *Wt;
    cudaGetSymbolAddress((void**)&x0, g_x0);
    cudaGetSymbolAddress((void**)&x1, g_x1);
    cudaGetSymbolAddress((void**)&q, g_q);
    cudaGetSymbolAddress((void**)&krel, g_krel);
    cudaGetSymbolAddress((void**)&vrel, g_vrel);
    cudaGetSymbolAddress((void**)&exb, g_exb);
    cudaGetSymbolAddress((void**)&den, g_den);
    cudaGetSymbolAddress((void**)&agg, g_agg);
    cudaGetSymbolAddress((void**)&Weff, g_Weff);
    cudaGetSymbolAddress((void**)&beff, g_beff);
    cudaGetSymbolAddress((void**)&Wt, g_Wt);

    const int smemTC = 2 * 128 * ASTRIDE * (int)sizeof(float);  // 132 KB
    cudaFuncSetAttribute(tc_gemm_kernel, cudaFuncAttributeMaxDynamicSharedMemorySize, smemTC);

    static const int relSrc[3]  = {0, 1, 0};
    static const int relDst[3]  = {1, 0, 0};
    static const int relRows[3] = {NU, NN, NU};
    static const int relOff[3]  = {0, NU, NU + NN};

    cudaMemcpyAsync(x0, x_user, (size_t)NU * CC * 4, cudaMemcpyDeviceToDevice, 0);
    cudaMemcpyAsync(x0 + (size_t)NU * CC, x_news, (size_t)NN * CC * 4, cudaMemcpyDeviceToDevice, 0);

    build_eff_kernel<<<12, 256, 0, 0>>>(Wk, bk, Wv, bv, a_rel, m_rel, Weff, beff);
    prep_wt_kernel<<<20, 256, 0, 0>>>(Wq, Wa, Weff, Wt);

    const int edgeBlocks = (EE + 7) / 8;

    for (int l = 0; l < NLAYER; l++) {
        float* xin  = (l == 0) ? x0 : x1;
        float* xout = (l == 0) ? x1 : x0;
        const float* xN = xin + (size_t)NU * CC;

        tc_gemm_kernel<<<(NU + 127) / 128, 256, smemTC, 0>>>(
            xin, Wt + (size_t)(l * 10 + 0) * CC * CC, bq + (l * 2 + 0) * CC,
            q, NU, 0, nullptr, nullptr);
        tc_gemm_kernel<<<(NN + 127) / 128, 256, smemTC, 0>>>(
            xN, Wt + (size_t)(l * 10 + 1) * CC * CC, bq + (l * 2 + 1) * CC,
            q + (size_t)NU * CC, NN, 0, nullptr, nullptr);

        for (int r = 0; r < 3; r++) {
            const float* xs_ = (relSrc[r] == 0) ? xin : xN;
            int rows = relRows[r];
            size_t bidx = (size_t)((l * 3 + r) * 2) * CC;
            tc_gemm_kernel<<<(rows + 127) / 128, 256, smemTC, 0>>>(
                xs_, Wt + (size_t)(l * 10 + 2 + 2 * r) * CC * CC, beff + bidx,
                krel + (size_t)relOff[r] * CC, rows, 0, nullptr, nullptr);
            tc_gemm_kernel<<<(rows + 127) / 128, 256, smemTC, 0>>>(
                xs_, Wt + (size_t)(l * 10 + 3 + 2 * r) * CC * CC, beff + bidx + CC,
                vrel + (size_t)relOff[r] * CC, rows, 0, nullptr, nullptr);
        }

        cudaMemsetAsync(agg, 0, (size_t)NT * CC * 4, 0);
        cudaMemsetAsync(den, 0, (size_t)3 * NU * 4 * 4, 0);

        for (int r = 0; r < 3; r++) {
            int dt = relDst[r];
            const float* qd = q + (size_t)((dt == 0) ? 0 : NU) * CC;
            float* aggd = agg + (size_t)((dt == 0) ? 0 : NU) * CC;
            edge_score_kernel<<<edgeBlocks, 256, 0, 0>>>(
                eis[r], qd, krel + (size_t)relOff[r] * CC,
                p_rel + (l * 3 + r) * 4, den + (size_t)r * NU * 4, exb + (size_t)r * EE * 4);
            edge_agg_kernel<<<edgeBlocks, 256, 0, 0>>>(
                eis[r], vrel + (size_t)relOff[r] * CC,
                den + (size_t)r * NU * 4, exb + (size_t)r * EE * 4, aggd);
        }

        tc_gemm_kernel<<<(NU + 127) / 128, 256, smemTC, 0>>>(
            agg, Wt + (size_t)(l * 10 + 8) * CC * CC, ba + (l * 2 + 0) * CC,
            xout, NU, 1, xin, skip + l * 2 + 0);
        tc_gemm_kernel<<<(NN + 127) / 128, 256, smemTC, 0>>>(
            agg + (size_t)NU * CC, Wt + (size_t)(l * 10 + 9) * CC * CC, ba + (l * 2 + 1) * CC,
            xout + (size_t)NU * CC, NN, 1, xN, skip + l * 2 + 1);
    }

    cudaMemcpyAsync(d_out, x0, (size_t)NT * CC * 4, cudaMemcpyDeviceToDevice, 0);
}

// round 4
// speedup vs baseline: 1.6134x; 1.3002x over previous
#include <cuda_runtime.h>
#include <cuda_fp16.h>
#include <math.h>
#include <stdint.h>

#define NU 100000
#define NN 20000
#define NT 120000
#define CC 128
#define EE 250000
#define NLAYER 2
#define NKV 220000   // NU + NN + NU
#define SA 136       // smem row stride in halves (conflict-free for frag loads)

// ---------------- scratch (device globals; no allocations allowed) ----------
__device__ float g_x0[NT * CC];
__device__ float g_x1[NT * CC];
__device__ float g_agg[NT * CC];
__device__ __half g_qh[NT * CC];
__device__ __half g_krelh[NKV * CC];
__device__ __half g_vrelh[NKV * CC];
__device__ float g_exb[3 * EE * 4];
__device__ float g_den[3 * NU * 4];
__device__ float g_Weff[12 * CC * CC];
__device__ float g_beff[12 * CC];
__device__ __half g_Wh[20 * CC * CC];   // fp16, transposed [n][k]

__device__ __forceinline__ float gelu_exact(float x) {
    return 0.5f * x * (1.0f + erff(x * 0.70710678118654752f));
}
__device__ __forceinline__ uint32_t smem_u32(const void* p) {
    uint32_t a;
    asm("{ .reg .u64 t; cvta.to.shared.u64 t, %1; cvt.u32.u64 %0, t; }" : "=r"(a) : "l"(p));
    return a;
}
__device__ __forceinline__ void cp16(__half* dst, const __half* src) {
    asm volatile("cp.async.cg.shared.global [%0], [%1], 16;"
                 :: "r"(smem_u32(dst)), "l"(src));
}
#define CP_COMMIT() asm volatile("cp.async.commit_group;" ::: "memory")
#define CP_WAIT0()  asm volatile("cp.async.wait_group 0;" ::: "memory")

// ---------------- effective relation weights (fp32) --------------------------
__global__ void build_eff_kernel(const float* __restrict__ Wk, const float* __restrict__ bk,
                                 const float* __restrict__ Wv, const float* __restrict__ bv,
                                 const float* __restrict__ a_rel, const float* __restrict__ m_rel,
                                 float* __restrict__ Weff, float* __restrict__ beff) {
    int b = blockIdx.x;
    int l = b / 6, rem = b % 6, r = rem >> 1, kv = rem & 1;
    int st = (r == 1) ? 1 : 0;
    const float* W   = (kv ? Wv : Wk) + (l * 2 + st) * CC * CC;
    const float* bi  = (kv ? bv : bk) + (l * 2 + st) * CC;
    const float* rel = (kv ? m_rel : a_rel) + (l * 3 + r) * 4096;
    float* out  = Weff + ((l * 3 + r) * 2 + kv) * CC * CC;
    float* bout = beff + ((l * 3 + r) * 2 + kv) * CC;

    __shared__ float rs[4096];
    for (int i = threadIdx.x; i < 4096; i += blockDim.x) rs[i] = rel[i];
    __syncthreads();

    for (int idx = threadIdx.x; idx < CC * CC; idx += blockDim.x) {
        int i = idx >> 7, j = idx & 127, h = j >> 5, e = j & 31;
        float s = 0.f;
#pragma unroll
        for (int d = 0; d < 32; d++)
            s += W[i * CC + h * 32 + d] * rs[h * 1024 + d * 32 + e];
        out[idx] = s;
    }
    if (threadIdx.x < CC) {
        int j = threadIdx.x, h = j >> 5, e = j & 31;
        float s = 0.f;
#pragma unroll
        for (int d = 0; d < 32; d++)
            s += bi[h * 32 + d] * rs[h * 1024 + d * 32 + e];
        bout[j] = s;
    }
}

// ---------------- weight prep: transpose + fp16 round ------------------------
// 20 mats: l*10 + {0,1}=Wq u/n, {2..7}=Weff (k,v)x(r0,r1,r2), {8,9}=Wa u/n
__global__ void prep_wh_kernel(const float* __restrict__ Wq, const float* __restrict__ Wa,
                               const float* __restrict__ Weff, __half* __restrict__ Wh) {
    int b = blockIdx.x;
    int l = b / 10, m = b % 10;
    const float* src;
    if (m < 2)       src = Wq + (size_t)(l * 2 + m) * CC * CC;
    else if (m < 8)  src = Weff + (size_t)((l * 3 + (m - 2) / 2) * 2 + ((m - 2) & 1)) * CC * CC;
    else             src = Wa + (size_t)(l * 2 + (m - 8)) * CC * CC;
    __half* out = Wh + (size_t)b * CC * CC;
    for (int idx = threadIdx.x; idx < CC * CC; idx += blockDim.x) {
        int n = idx >> 7, k = idx & 127;
        out[idx] = __float2half(src[k * CC + n]);   // [n][k] = W[k][n]
    }
}

// ---------------- shared MMA compute: 128x128, 16 warps (4m x 4n) ------------
__device__ __forceinline__ void mma_tile_128(const __half* As, const __half* Bs,
                                             float acc[2][4][4], int wm, int wn,
                                             int g, int t) {
    const uint32_t* A32 = (const uint32_t*)As;
    const uint32_t* B32 = (const uint32_t*)Bs;
#pragma unroll
    for (int k0 = 0; k0 < CC; k0 += 16) {
        uint32_t a[2][4];
#pragma unroll
        for (int m = 0; m < 2; m++) {
            int ra = (wm * 32 + m * 16 + g) * (SA / 2) + (k0 >> 1) + t;
            a[m][0] = A32[ra];
            a[m][1] = A32[ra + 8 * (SA / 2)];
            a[m][2] = A32[ra + 4];
            a[m][3] = A32[ra + 8 * (SA / 2) + 4];
        }
        uint32_t b[4][2];
#pragma unroll
        for (int n = 0; n < 4; n++) {
            int rb = (wn * 32 + n * 8 + g) * (SA / 2) + (k0 >> 1) + t;
            b[n][0] = B32[rb];
            b[n][1] = B32[rb + 4];
        }
#pragma unroll
        for (int m = 0; m < 2; m++)
#pragma unroll
            for (int n = 0; n < 4; n++) {
                float* c = acc[m][n];
                asm volatile(
                    "mma.sync.aligned.m16n8k16.row.col.f32.f16.f16.f32 "
                    "{%0,%1,%2,%3}, {%4,%5,%6,%7}, {%8,%9}, {%0,%1,%2,%3};"
                    : "+f"(c[0]), "+f"(c[1]), "+f"(c[2]), "+f"(c[3])
                    : "r"(a[m][0]), "r"(a[m][1]), "r"(a[m][2]), "r"(a[m][3]),
                      "r"(b[n][0]), "r"(b[n][1]));
            }
    }
}

__device__ __forceinline__ void prefetch_B(__half* Bs, const __half* W, int tid) {
#pragma unroll
    for (int it = 0; it < 4; it++) {
        int c = tid + it * 512;          // 16B chunks, 2048 total
        int n = c >> 4, cc = c & 15;
        cp16(Bs + n * SA + cc * 8, W + n * CC + cc * 8);
    }
    CP_COMMIT();
}

// ---------------- fused projection kernel (multi-weight, fp16 out) -----------
struct ProjArgs {
    const float* X;
    int N;
    int nW;
    const __half* W[5];
    const float* bias[5];
    __half* out[5];
};

__global__ __launch_bounds__(512, 1)
void proj_kernel(ProjArgs pa) {
    extern __shared__ __half smh[];
    __half* As  = smh;                 // 128*136
    __half* Bs0 = smh + 128 * SA;
    __half* Bs1 = smh + 2 * 128 * SA;
    int tid = threadIdx.x;
    int row0 = blockIdx.x * 128;

    prefetch_B(Bs0, pa.W[0], tid);

    // stage A: fp32 -> fp16
    const float4* X4 = (const float4*)pa.X;
#pragma unroll
    for (int it = 0; it < 8; it++) {
        int idx = tid + it * 512;           // 0..4095 float4s
        int row = idx >> 5, q4 = idx & 31;
        int gr = row0 + row;
        float4 v = make_float4(0.f, 0.f, 0.f, 0.f);
        if (gr < pa.N) v = X4[gr * 32 + q4];
        __half2 h0 = __floats2half2_rn(v.x, v.y);
        __half2 h1 = __floats2half2_rn(v.z, v.w);
        uint2 u;
        u.x = *(uint32_t*)&h0; u.y = *(uint32_t*)&h1;
        *(uint2*)(As + row * SA + q4 * 4) = u;
    }
    CP_WAIT0();
    __syncthreads();

    int wid = tid >> 5, lane = tid & 31;
    int wm = wid & 3, wn = wid >> 2;
    int g = lane >> 2, t = lane & 3;

    for (int w = 0; w < pa.nW; w++) {
        __half* Bcur = (w & 1) ? Bs1 : Bs0;
        if (w + 1 < pa.nW) prefetch_B((w & 1) ? Bs0 : Bs1, pa.W[w + 1], tid);

        float acc[2][4][4];
#pragma unroll
        for (int m = 0; m < 2; m++)
#pragma unroll
            for (int n = 0; n < 4; n++)
#pragma unroll
                for (int c = 0; c < 4; c++) acc[m][n][c] = 0.f;

        mma_tile_128(As, Bcur, acc, wm, wn, g, t);

        const float* bias = pa.bias[w];
        __half* out = pa.out[w];
#pragma unroll
        for (int m = 0; m < 2; m++) {
#pragma unroll
            for (int n = 0; n < 4; n++) {
                int col = wn * 32 + n * 8 + 2 * t;
                float bx = bias[col], by = bias[col + 1];
                int r0 = row0 + wm * 32 + m * 16 + g;
                if (r0 < pa.N) {
                    __half2 o = __floats2half2_rn(acc[m][n][0] + bx, acc[m][n][1] + by);
                    *(__half2*)&out[(size_t)r0 * CC + col] = o;
                }
                int r1 = r0 + 8;
                if (r1 < pa.N) {
                    __half2 o = __floats2half2_rn(acc[m][n][2] + bx, acc[m][n][3] + by);
                    *(__half2*)&out[(size_t)r1 * CC + col] = o;
                }
            }
        }
        if (w + 1 < pa.nW) { CP_WAIT0(); __syncthreads(); }
    }
}

// ---------------- output GEMM: gelu(A) @ W + b, skip blend + relu, fp32 out --
__global__ __launch_bounds__(512, 1)
void out_kernel(const float* __restrict__ Xagg, const __half* __restrict__ W,
                const float* __restrict__ bias, float* __restrict__ Y, int N,
                const float* __restrict__ xold, const float* __restrict__ skipPtr) {
    extern __shared__ __half smh[];
    __half* As = smh;
    __half* Bs = smh + 128 * SA;
    int tid = threadIdx.x;
    int row0 = blockIdx.x * 128;

    prefetch_B(Bs, W, tid);

    const float4* X4 = (const float4*)Xagg;
#pragma unroll
    for (int it = 0; it < 8; it++) {
        int idx = tid + it * 512;
        int row = idx >> 5, q4 = idx & 31;
        int gr = row0 + row;
        float4 v = make_float4(0.f, 0.f, 0.f, 0.f);
        if (gr < N) {
            v = X4[gr * 32 + q4];
            v.x = gelu_exact(v.x); v.y = gelu_exact(v.y);
            v.z = gelu_exact(v.z); v.w = gelu_exact(v.w);
        }
        __half2 h0 = __floats2half2_rn(v.x, v.y);
        __half2 h1 = __floats2half2_rn(v.z, v.w);
        uint2 u;
        u.x = *(uint32_t*)&h0; u.y = *(uint32_t*)&h1;
        *(uint2*)(As + row * SA + q4 * 4) = u;
    }
    CP_WAIT0();
    __syncthreads();

    int wid = tid >> 5, lane = tid & 31;
    int wm = wid & 3, wn = wid >> 2;
    int g = lane >> 2, t = lane & 3;

    float acc[2][4][4];
#pragma unroll
    for (int m = 0; m < 2; m++)
#pragma unroll
        for (int n = 0; n < 4; n++)
#pragma unroll
            for (int c = 0; c < 4; c++) acc[m][n][c] = 0.f;

    mma_tile_128(As, Bs, acc, wm, wn, g, t);

    float s = *skipPtr;
    float aS = 1.f / (1.f + expf(-s));
    float bS = 1.f - aS;
#pragma unroll
    for (int m = 0; m < 2; m++) {
#pragma unroll
        for (int n = 0; n < 4; n++) {
            int col = wn * 32 + n * 8 + 2 * t;
            float bx = bias[col], by = bias[col + 1];
            int r0 = row0 + wm * 32 + m * 16 + g;
            if (r0 < N) {
                float2 xo = *(const float2*)&xold[(size_t)r0 * CC + col];
                float2 o;
                o.x = fmaxf(fmaf(aS, acc[m][n][0] + bx, bS * xo.x), 0.f);
                o.y = fmaxf(fmaf(aS, acc[m][n][1] + by, bS * xo.y), 0.f);
                *(float2*)&Y[(size_t)r0 * CC + col] = o;
            }
            int r1 = r0 + 8;
            if (r1 < N) {
                float2 xo = *(const float2*)&xold[(size_t)r1 * CC + col];
                float2 o;
                o.x = fmaxf(fmaf(aS, acc[m][n][2] + bx, bS * xo.x), 0.f);
                o.y = fmaxf(fmaf(aS, acc[m][n][3] + by, bS * xo.y), 0.f);
                *(float2*)&Y[(size_t)r1 * CC + col] = o;
            }
        }
    }
}

// ---------------- edge pass A (all 3 relations): score->exp->den -------------
__global__ void edge_score_all(const int* __restrict__ ei0, const int* __restrict__ ei1,
                               const int* __restrict__ ei2,
                               const __half* __restrict__ qh, const __half* __restrict__ krelh,
                               const float* __restrict__ prel,   // + l*12
                               float* __restrict__ den, float* __restrict__ exb) {
    int w = (blockIdx.x * blockDim.x + threadIdx.x) >> 5;
    int lane = threadIdx.x & 31;
    if (w >= 3 * EE) return;
    int r = w / EE;
    int e = w - r * EE;
    const int* ei = (r == 0) ? ei0 : ((r == 1) ? ei1 : ei2);
    int src = ei[e], dst = ei[EE + e];
    int qOff = (r == 0) ? NU : 0;
    int kOff = (r == 0) ? 0 : ((r == 1) ? NU : (NU + NN));

    uint2 qa = *(const uint2*)(qh + (size_t)(qOff + dst) * CC + lane * 4);
    uint2 ka = *(const uint2*)(krelh + (size_t)(kOff + src) * CC + lane * 4);
    float2 q0 = __half22float2(*(__half2*)&qa.x), q1 = __half22float2(*(__half2*)&qa.y);
    float2 k0 = __half22float2(*(__half2*)&ka.x), k1 = __half22float2(*(__half2*)&ka.y);
    float s = q0.x * k0.x + q0.y * k0.y + q1.x * k1.x + q1.y * k1.y;
    s += __shfl_xor_sync(0xffffffffu, s, 1);
    s += __shfl_xor_sync(0xffffffffu, s, 2);
    s += __shfl_xor_sync(0xffffffffu, s, 4);
    if ((lane & 7) == 0) {
        int h = lane >> 3;
        float sc = s * prel[r * 4 + h] * 0.17677669529663689f;
        float ex = expf(sc);
        exb[((size_t)r * EE + e) * 4 + h] = ex;
        atomicAdd(&den[((size_t)r * NU + dst) * 4 + h], ex);
    }
}

// ---------------- edge pass B (all 3 relations): alpha scatter ---------------
__global__ void edge_agg_all(const int* __restrict__ ei0, const int* __restrict__ ei1,
                             const int* __restrict__ ei2,
                             const __half* __restrict__ vrelh,
                             const float* __restrict__ den, const float* __restrict__ exb,
                             float* __restrict__ agg) {
    int w = (blockIdx.x * blockDim.x + threadIdx.x) >> 5;
    int lane = threadIdx.x & 31;
    if (w >= 3 * EE) return;
    int r = w / EE;
    int e = w - r * EE;
    const int* ei = (r == 0) ? ei0 : ((r == 1) ? ei1 : ei2);
    int src = ei[e], dst = ei[EE + e];
    int vOff = (r == 0) ? 0 : ((r == 1) ? NU : (NU + NN));
    int dOff = (r == 0) ? NU : 0;
    int h = lane >> 3;

    float alpha = exb[((size_t)r * EE + e) * 4 + h]
                / (den[((size_t)r * NU + dst) * 4 + h] + 1e-16f);
    uint2 va = *(const uint2*)(vrelh + (size_t)(vOff + src) * CC + lane * 4);
    float2 v0 = __half22float2(*(__half2*)&va.x), v1 = __half22float2(*(__half2*)&va.y);
    float* p = &agg[(size_t)(dOff + dst) * CC + lane * 4];
    asm volatile("red.global.add.v4.f32 [%0], {%1, %2, %3, %4};"
                 :: "l"(p), "f"(v0.x * alpha), "f"(v0.y * alpha),
                    "f"(v1.x * alpha), "f"(v1.y * alpha)
                 : "memory");
}

// ---------------- host orchestration ----------------------------------------
extern "C" void kernel_launch(void* const* d_in, const int* in_sizes, int n_in,
                              void* d_out, int out_size) {
    const float* x_user = (const float*)d_in[0];
    const float* x_news = (const float*)d_in[1];
    const int* ei0 = (const int*)d_in[2];
    const int* ei1 = (const int*)d_in[3];
    const int* ei2 = (const int*)d_in[4];
    const float* Wk = (const float*)d_in[5];
    const float* bk = (const float*)d_in[6];
    const float* Wq = (const float*)d_in[7];
    const float* bq = (const float*)d_in[8];
    const float* Wv = (const float*)d_in[9];
    const float* bv = (const float*)d_in[10];
    const float* Wa = (const float*)d_in[11];
    const float* ba = (const float*)d_in[12];
    const float* skip = (const float*)d_in[13];
    const float* a_rel = (const float*)d_in[14];
    const float* m_rel = (const float*)d_in[15];
    const float* p_rel = (const float*)d_in[16];

    float *x0, *x1, *agg, *exb, *den, *Weff, *beff;
    __half *qh, *krelh, *vrelh, *Wh;
    cudaGetSymbolAddress((void**)&x0, g_x0);
    cudaGetSymbolAddress((void**)&x1, g_x1);
    cudaGetSymbolAddress((void**)&agg, g_agg);
    cudaGetSymbolAddress((void**)&qh, g_qh);
    cudaGetSymbolAddress((void**)&krelh, g_krelh);
    cudaGetSymbolAddress((void**)&vrelh, g_vrelh);
    cudaGetSymbolAddress((void**)&exb, g_exb);
    cudaGetSymbolAddress((void**)&den, g_den);
    cudaGetSymbolAddress((void**)&Weff, g_Weff);
    cudaGetSymbolAddress((void**)&beff, g_beff);
    cudaGetSymbolAddress((void**)&Wh, g_Wh);

    const int smemProj = 3 * 128 * SA * 2;   // ~102 KB
    const int smemOut  = 2 * 128 * SA * 2;   // ~68 KB
    cudaFuncSetAttribute(proj_kernel, cudaFuncAttributeMaxDynamicSharedMemorySize, smemProj);
    cudaFuncSetAttribute(out_kernel, cudaFuncAttributeMaxDynamicSharedMemorySize, smemOut);

    cudaMemcpyAsync(x0, x_user, (size_t)NU * CC * 4, cudaMemcpyDeviceToDevice, 0);
    cudaMemcpyAsync(x0 + (size_t)NU * CC, x_news, (size_t)NN * CC * 4, cudaMemcpyDeviceToDevice, 0);

    build_eff_kernel<<<12, 256, 0, 0>>>(Wk, bk, Wv, bv, a_rel, m_rel, Weff, beff);
    prep_wh_kernel<<<20, 256, 0, 0>>>(Wq, Wa, Weff, Wh);

    const int gridU = (NU + 127) / 128;   // 782
    const int gridN = (NN + 127) / 128;   // 157
    const int edgeBlocks = (3 * EE + 7) / 8;

    for (int l = 0; l < NLAYER; l++) {
        float* xin  = (l == 0) ? x0 : x1;
        float* xout = (l == 0) ? x1 : x0;
        const float* xN = xin + (size_t)NU * CC;
        size_t wl = (size_t)l * 10 * CC * CC;

        // fused user projections: q, k_r0, v_r0, k_r2, v_r2
        {
            ProjArgs pa;
            pa.X = xin; pa.N = NU; pa.nW = 5;
            pa.W[0] = Wh + wl + 0 * CC * CC;  pa.bias[0] = bq + (l * 2 + 0) * CC;                 pa.out[0] = qh;
            pa.W[1] = Wh + wl + 2 * CC * CC;  pa.bias[1] = beff + ((l * 3 + 0) * 2 + 0) * CC;     pa.out[1] = krelh;
            pa.W[2] = Wh + wl + 3 * CC * CC;  pa.bias[2] = beff + ((l * 3 + 0) * 2 + 1) * CC;     pa.out[2] = vrelh;
            pa.W[3] = Wh + wl + 6 * CC * CC;  pa.bias[3] = beff + ((l * 3 + 2) * 2 + 0) * CC;     pa.out[3] = krelh + (size_t)(NU + NN) * CC;
            pa.W[4] = Wh + wl + 7 * CC * CC;  pa.bias[4] = beff + ((l * 3 + 2) * 2 + 1) * CC;     pa.out[4] = vrelh + (size_t)(NU + NN) * CC;
            proj_kernel<<<gridU, 512, smemProj, 0>>>(pa);
        }
        // fused news projections: q, k_r1, v_r1
        {
            ProjArgs pa;
            pa.X = xN; pa.N = NN; pa.nW = 3;
            pa.W[0] = Wh + wl + 1 * CC * CC;  pa.bias[0] = bq + (l * 2 + 1) * CC;                 pa.out[0] = qh + (size_t)NU * CC;
            pa.W[1] = Wh + wl + 4 * CC * CC;  pa.bias[1] = beff + ((l * 3 + 1) * 2 + 0) * CC;     pa.out[1] = krelh + (size_t)NU * CC;
            pa.W[2] = Wh + wl + 5 * CC * CC;  pa.bias[2] = beff + ((l * 3 + 1) * 2 + 1) * CC;     pa.out[2] = vrelh + (size_t)NU * CC;
            proj_kernel<<<gridN, 512, smemProj, 0>>>(pa);
        }

        cudaMemsetAsync(agg, 0, (size_t)NT * CC * 4, 0);
        cudaMemsetAsync(den, 0, (size_t)3 * NU * 4 * 4, 0);

        edge_score_all<<<edgeBlocks, 256, 0, 0>>>(ei0, ei1, ei2, qh, krelh,
                                                  p_rel + l * 12, den, exb);
        edge_agg_all<<<edgeBlocks, 256, 0, 0>>>(ei0, ei1, ei2, vrelh, den, exb, agg);

        out_kernel<<<gridU, 512, smemOut, 0>>>(
            agg, Wh + wl + 8 * CC * CC, ba + (l * 2 + 0) * CC,
            xout, NU, xin, skip + l * 2 + 0);
        out_kernel<<<gridN, 512, smemOut, 0>>>(
            agg + (size_t)NU * CC, Wh + wl + 9 * CC * CC, ba + (l * 2 + 1) * CC,
            xout + (size_t)NU * CC, NN, xN, skip + l * 2 + 1);
    }

    cudaMemcpyAsync(d_out, x0, (size_t)NT * CC * 4, cudaMemcpyDeviceToDevice, 0);
}

// round 5
// speedup vs baseline: 1.9470x; 1.2067x over previous
#include <cuda_runtime.h>
#include <cuda_fp16.h>
#include <math.h>
#include <stdint.h>

#define NU 100000
#define NN 20000
#define NT 120000
#define CC 128
#define EE 250000
#define NLAYER 2
#define NKV 220000   // NU + NN + NU
#define SA 136       // smem row stride in halves (conflict-free frag loads)

// ---------------- scratch (device globals; no allocations allowed) ----------
__device__ float g_x1[NT * CC];
__device__ __half g_qh[NT * CC];
__device__ __half g_krelh[NKV * CC];
__device__ __half g_vrelh[NKV * CC];
__device__ float g_aggr[NKV * CC];     // unnormalized per-relation agg: r0(NN) r1(NU) r2(NU)
__device__ float g_den[3 * NU * 4];
__device__ float g_Weff[12 * CC * CC];
__device__ float g_beff[12 * CC];
__device__ __half g_Wh[20 * CC * CC];  // fp16, transposed [n][k]

__device__ __forceinline__ float gelu_exact(float x) {
    return 0.5f * x * (1.0f + erff(x * 0.70710678118654752f));
}
__device__ __forceinline__ uint32_t smem_u32(const void* p) {
    uint32_t a;
    asm("{ .reg .u64 t; cvta.to.shared.u64 t, %1; cvt.u32.u64 %0, t; }" : "=r"(a) : "l"(p));
    return a;
}
__device__ __forceinline__ void cp16(__half* dst, const __half* src) {
    asm volatile("cp.async.cg.shared.global [%0], [%1], 16;"
                 :: "r"(smem_u32(dst)), "l"(src));
}
#define CP_COMMIT() asm volatile("cp.async.commit_group;" ::: "memory")
#define CP_WAIT0()  asm volatile("cp.async.wait_group 0;" ::: "memory")

// ---------------- effective relation weights (fp32) --------------------------
__global__ void build_eff_kernel(const float* __restrict__ Wk, const float* __restrict__ bk,
                                 const float* __restrict__ Wv, const float* __restrict__ bv,
                                 const float* __restrict__ a_rel, const float* __restrict__ m_rel,
                                 float* __restrict__ Weff, float* __restrict__ beff) {
    int b = blockIdx.x;
    int l = b / 6, rem = b % 6, r = rem >> 1, kv = rem & 1;
    int st = (r == 1) ? 1 : 0;
    const float* W   = (kv ? Wv : Wk) + (l * 2 + st) * CC * CC;
    const float* bi  = (kv ? bv : bk) + (l * 2 + st) * CC;
    const float* rel = (kv ? m_rel : a_rel) + (l * 3 + r) * 4096;
    float* out  = Weff + ((l * 3 + r) * 2 + kv) * CC * CC;
    float* bout = beff + ((l * 3 + r) * 2 + kv) * CC;

    __shared__ float rs[4096];
    for (int i = threadIdx.x; i < 4096; i += blockDim.x) rs[i] = rel[i];
    __syncthreads();

    for (int idx = threadIdx.x; idx < CC * CC; idx += blockDim.x) {
        int i = idx >> 7, j = idx & 127, h = j >> 5, e = j & 31;
        float s = 0.f;
#pragma unroll
        for (int d = 0; d < 32; d++)
            s += W[i * CC + h * 32 + d] * rs[h * 1024 + d * 32 + e];
        out[idx] = s;
    }
    if (threadIdx.x < CC) {
        int j = threadIdx.x, h = j >> 5, e = j & 31;
        float s = 0.f;
#pragma unroll
        for (int d = 0; d < 32; d++)
            s += bi[h * 32 + d] * rs[h * 1024 + d * 32 + e];
        bout[j] = s;
    }
}

// ---------------- weight prep: transpose + fp16 round ------------------------
__global__ void prep_wh_kernel(const float* __restrict__ Wq, const float* __restrict__ Wa,
                               const float* __restrict__ Weff, __half* __restrict__ Wh) {
    int b = blockIdx.x;
    int l = b / 10, m = b % 10;
    const float* src;
    if (m < 2)       src = Wq + (size_t)(l * 2 + m) * CC * CC;
    else if (m < 8)  src = Weff + (size_t)((l * 3 + (m - 2) / 2) * 2 + ((m - 2) & 1)) * CC * CC;
    else             src = Wa + (size_t)(l * 2 + (m - 8)) * CC * CC;
    __half* out = Wh + (size_t)b * CC * CC;
    for (int idx = threadIdx.x; idx < CC * CC; idx += blockDim.x) {
        int n = idx >> 7, k = idx & 127;
        out[idx] = __float2half(src[k * CC + n]);   // [n][k] = W[k][n]
    }
}

// ---------------- MMA compute: 128x128 tile, 8 warps (4m x 2n), 32x64/warp ---
__device__ __forceinline__ void mma_tile_128(const __half* As, const __half* Bs,
                                             float acc[2][8][4], int wm, int wn,
                                             int g, int t) {
    const uint32_t* A32 = (const uint32_t*)As;
    const uint32_t* B32 = (const uint32_t*)Bs;
#pragma unroll
    for (int k0 = 0; k0 < CC; k0 += 16) {
        uint32_t a[2][4];
#pragma unroll
        for (int m = 0; m < 2; m++) {
            int ra = (wm * 32 + m * 16 + g) * (SA / 2) + (k0 >> 1) + t;
            a[m][0] = A32[ra];
            a[m][1] = A32[ra + 8 * (SA / 2)];
            a[m][2] = A32[ra + 4];
            a[m][3] = A32[ra + 8 * (SA / 2) + 4];
        }
        uint32_t b[8][2];
#pragma unroll
        for (int n = 0; n < 8; n++) {
            int rb = (wn * 64 + n * 8 + g) * (SA / 2) + (k0 >> 1) + t;
            b[n][0] = B32[rb];
            b[n][1] = B32[rb + 4];
        }
#pragma unroll
        for (int m = 0; m < 2; m++)
#pragma unroll
            for (int n = 0; n < 8; n++) {
                float* c = acc[m][n];
                asm volatile(
                    "mma.sync.aligned.m16n8k16.row.col.f32.f16.f16.f32 "
                    "{%0,%1,%2,%3}, {%4,%5,%6,%7}, {%8,%9}, {%0,%1,%2,%3};"
                    : "+f"(c[0]), "+f"(c[1]), "+f"(c[2]), "+f"(c[3])
                    : "r"(a[m][0]), "r"(a[m][1]), "r"(a[m][2]), "r"(a[m][3]),
                      "r"(b[n][0]), "r"(b[n][1]));
            }
    }
}

__device__ __forceinline__ void prefetch_B(__half* Bs, const __half* W, int tid) {
#pragma unroll
    for (int it = 0; it < 8; it++) {
        int c = tid + it * 256;          // 2048 16B chunks
        int n = c >> 4, cc = c & 15;
        cp16(Bs + n * SA + cc * 8, W + n * CC + cc * 8);
    }
    CP_COMMIT();
}

// ---------------- fused projection kernel (multi-weight, fp16 out) -----------
struct ProjArgs {
    const float* X;
    int N;
    int nW;
    const __half* W[5];
    const float* bias[5];
    __half* out[5];
};

__global__ __launch_bounds__(256, 2)
void proj_kernel(ProjArgs pa) {
    extern __shared__ __half smh[];
    __half* As  = smh;
    __half* Bs0 = smh + 128 * SA;
    __half* Bs1 = smh + 2 * 128 * SA;
    int tid = threadIdx.x;
    int row0 = blockIdx.x * 128;

    prefetch_B(Bs0, pa.W[0], tid);

    const float4* X4 = (const float4*)pa.X;
#pragma unroll
    for (int it = 0; it < 16; it++) {
        int idx = tid + it * 256;           // 0..4095 float4s
        int row = idx >> 5, q4 = idx & 31;
        int gr = row0 + row;
        float4 v = make_float4(0.f, 0.f, 0.f, 0.f);
        if (gr < pa.N) v = X4[gr * 32 + q4];
        __half2 h0 = __floats2half2_rn(v.x, v.y);
        __half2 h1 = __floats2half2_rn(v.z, v.w);
        uint2 u;
        u.x = *(uint32_t*)&h0; u.y = *(uint32_t*)&h1;
        *(uint2*)(As + row * SA + q4 * 4) = u;
    }
    CP_WAIT0();
    __syncthreads();

    int wid = tid >> 5, lane = tid & 31;
    int wm = wid & 3, wn = wid >> 2;
    int g = lane >> 2, t = lane & 3;

    for (int w = 0; w < pa.nW; w++) {
        __half* Bcur = (w & 1) ? Bs1 : Bs0;
        if (w + 1 < pa.nW) prefetch_B((w & 1) ? Bs0 : Bs1, pa.W[w + 1], tid);

        float acc[2][8][4];
#pragma unroll
        for (int m = 0; m < 2; m++)
#pragma unroll
            for (int n = 0; n < 8; n++)
#pragma unroll
                for (int c = 0; c < 4; c++) acc[m][n][c] = 0.f;

        mma_tile_128(As, Bcur, acc, wm, wn, g, t);

        const float* bias = pa.bias[w];
        __half* out = pa.out[w];
#pragma unroll
        for (int m = 0; m < 2; m++) {
#pragma unroll
            for (int n = 0; n < 8; n++) {
                int col = wn * 64 + n * 8 + 2 * t;
                float bx = bias[col], by = bias[col + 1];
                int r0 = row0 + wm * 32 + m * 16 + g;
                if (r0 < pa.N) {
                    __half2 o = __floats2half2_rn(acc[m][n][0] + bx, acc[m][n][1] + by);
                    *(__half2*)&out[(size_t)r0 * CC + col] = o;
                }
                int r1 = r0 + 8;
                if (r1 < pa.N) {
                    __half2 o = __floats2half2_rn(acc[m][n][2] + bx, acc[m][n][3] + by);
                    *(__half2*)&out[(size_t)r1 * CC + col] = o;
                }
            }
        }
        if (w + 1 < pa.nW) { CP_WAIT0(); __syncthreads(); }
    }
}

// ---------------- output GEMM: normalize+combine+gelu fused A-stage ----------
// A[row] = gelu(aggA[row]/(denA+eps) [+ aggB[row]/(denB+eps)]); Y = A@W + b,
// then sigmoid-skip blend with xold + relu (fp32 out).
__global__ __launch_bounds__(256, 2)
void out_kernel(const float* __restrict__ aggA, const float* __restrict__ denA,
                const float* __restrict__ aggB, const float* __restrict__ denB,
                const __half* __restrict__ W, const float* __restrict__ bias,
                float* __restrict__ Y, int N,
                const float* __restrict__ xold, const float* __restrict__ skipPtr) {
    extern __shared__ __half smh[];
    __half* As = smh;
    __half* Bs = smh + 128 * SA;
    int tid = threadIdx.x;
    int row0 = blockIdx.x * 128;

    prefetch_B(Bs, W, tid);

    const float4* A4 = (const float4*)aggA;
    const float4* B4 = (const float4*)aggB;
#pragma unroll
    for (int it = 0; it < 16; it++) {
        int idx = tid + it * 256;
        int row = idx >> 5, q4 = idx & 31;
        int gr = row0 + row;
        float4 v = make_float4(0.f, 0.f, 0.f, 0.f);
        if (gr < N) {
            int h = q4 >> 3;
            float iA = 1.f / (denA[gr * 4 + h] + 1e-16f);
            float4 a = A4[(size_t)gr * 32 + q4];
            v.x = a.x * iA; v.y = a.y * iA; v.z = a.z * iA; v.w = a.w * iA;
            if (aggB) {
                float iB = 1.f / (denB[gr * 4 + h] + 1e-16f);
                float4 b = B4[(size_t)gr * 32 + q4];
                v.x += b.x * iB; v.y += b.y * iB; v.z += b.z * iB; v.w += b.w * iB;
            }
            v.x = gelu_exact(v.x); v.y = gelu_exact(v.y);
            v.z = gelu_exact(v.z); v.w = gelu_exact(v.w);
        }
        __half2 h0 = __floats2half2_rn(v.x, v.y);
        __half2 h1 = __floats2half2_rn(v.z, v.w);
        uint2 u;
        u.x = *(uint32_t*)&h0; u.y = *(uint32_t*)&h1;
        *(uint2*)(As + row * SA + q4 * 4) = u;
    }
    CP_WAIT0();
    __syncthreads();

    int wid = tid >> 5, lane = tid & 31;
    int wm = wid & 3, wn = wid >> 2;
    int g = lane >> 2, t = lane & 3;

    float acc[2][8][4];
#pragma unroll
    for (int m = 0; m < 2; m++)
#pragma unroll
        for (int n = 0; n < 8; n++)
#pragma unroll
            for (int c = 0; c < 4; c++) acc[m][n][c] = 0.f;

    mma_tile_128(As, Bs, acc, wm, wn, g, t);

    float s = *skipPtr;
    float aS = 1.f / (1.f + expf(-s));
    float bS = 1.f - aS;
#pragma unroll
    for (int m = 0; m < 2; m++) {
#pragma unroll
        for (int n = 0; n < 8; n++) {
            int col = wn * 64 + n * 8 + 2 * t;
            float bx = bias[col], by = bias[col + 1];
            int r0 = row0 + wm * 32 + m * 16 + g;
            if (r0 < N) {
                float2 xo = *(const float2*)&xold[(size_t)r0 * CC + col];
                float2 o;
                o.x = fmaxf(fmaf(aS, acc[m][n][0] + bx, bS * xo.x), 0.f);
                o.y = fmaxf(fmaf(aS, acc[m][n][1] + by, bS * xo.y), 0.f);
                *(float2*)&Y[(size_t)r0 * CC + col] = o;
            }
            int r1 = r0 + 8;
            if (r1 < N) {
                float2 xo = *(const float2*)&xold[(size_t)r1 * CC + col];
                float2 o;
                o.x = fmaxf(fmaf(aS, acc[m][n][2] + bx, bS * xo.x), 0.f);
                o.y = fmaxf(fmaf(aS, acc[m][n][3] + by, bS * xo.y), 0.f);
                *(float2*)&Y[(size_t)r1 * CC + col] = o;
            }
        }
    }
}

// ---------------- single-pass edge kernel (all 3 relations) ------------------
// score -> ex -> scatter ex*v into per-relation agg, ex into den.
__global__ void edge_fused(const int* __restrict__ ei0, const int* __restrict__ ei1,
                           const int* __restrict__ ei2,
                           const __half* __restrict__ qh, const __half* __restrict__ krelh,
                           const __half* __restrict__ vrelh,
                           const float* __restrict__ prel,   // + l*12
                           float* __restrict__ den, float* __restrict__ aggr) {
    int w = (blockIdx.x * blockDim.x + threadIdx.x) >> 5;
    int lane = threadIdx.x & 31;
    if (w >= 3 * EE) return;
    int r = w / EE;
    int e = w - r * EE;
    const int* ei = (r == 0) ? ei0 : ((r == 1) ? ei1 : ei2);
    int src = ei[e], dst = ei[EE + e];
    int qOff  = (r == 0) ? NU : 0;
    int kvOff = (r == 0) ? 0 : ((r == 1) ? NU : (NU + NN));
    int aOff  = (r == 0) ? 0 : ((r == 1) ? NN : (NN + NU));

    uint2 qa = *(const uint2*)(qh + (size_t)(qOff + dst) * CC + lane * 4);
    uint2 ka = *(const uint2*)(krelh + (size_t)(kvOff + src) * CC + lane * 4);
    float2 q0 = __half22float2(*(__half2*)&qa.x), q1 = __half22float2(*(__half2*)&qa.y);
    float2 k0 = __half22float2(*(__half2*)&ka.x), k1 = __half22float2(*(__half2*)&ka.y);
    float s = q0.x * k0.x + q0.y * k0.y + q1.x * k1.x + q1.y * k1.y;
    s += __shfl_xor_sync(0xffffffffu, s, 1);
    s += __shfl_xor_sync(0xffffffffu, s, 2);
    s += __shfl_xor_sync(0xffffffffu, s, 4);

    int h = lane >> 3;
    float sc = s * prel[r * 4 + h] * 0.17677669529663689f;
    float ex = expf(sc);

    uint2 va = *(const uint2*)(vrelh + (size_t)(kvOff + src) * CC + lane * 4);
    float2 v0 = __half22float2(*(__half2*)&va.x), v1 = __half22float2(*(__half2*)&va.y);
    float* p = &aggr[(size_t)(aOff + dst) * CC + lane * 4];
    asm volatile("red.global.add.v4.f32 [%0], {%1, %2, %3, %4};"
                 :: "l"(p), "f"(v0.x * ex), "f"(v0.y * ex),
                    "f"(v1.x * ex), "f"(v1.y * ex)
                 : "memory");
    if ((lane & 7) == 0)
        atomicAdd(&den[((size_t)r * NU + dst) * 4 + h], ex);
}

// ---------------- host orchestration ----------------------------------------
extern "C" void kernel_launch(void* const* d_in, const int* in_sizes, int n_in,
                              void* d_out, int out_size) {
    const float* x_user = (const float*)d_in[0];
    const float* x_news = (const float*)d_in[1];
    const int* ei0 = (const int*)d_in[2];
    const int* ei1 = (const int*)d_in[3];
    const int* ei2 = (const int*)d_in[4];
    const float* Wk = (const float*)d_in[5];
    const float* bk = (const float*)d_in[6];
    const float* Wq = (const float*)d_in[7];
    const float* bq = (const float*)d_in[8];
    const float* Wv = (const float*)d_in[9];
    const float* bv = (const float*)d_in[10];
    const float* Wa = (const float*)d_in[11];
    const float* ba = (const float*)d_in[12];
    const float* skip = (const float*)d_in[13];
    const float* a_rel = (const float*)d_in[14];
    const float* m_rel = (const float*)d_in[15];
    const float* p_rel = (const float*)d_in[16];

    float *x1, *aggr, *den, *Weff, *beff;
    __half *qh, *krelh, *vrelh, *Wh;
    cudaGetSymbolAddress((void**)&x1, g_x1);
    cudaGetSymbolAddress((void**)&aggr, g_aggr);
    cudaGetSymbolAddress((void**)&qh, g_qh);
    cudaGetSymbolAddress((void**)&krelh, g_krelh);
    cudaGetSymbolAddress((void**)&vrelh, g_vrelh);
    cudaGetSymbolAddress((void**)&den, g_den);
    cudaGetSymbolAddress((void**)&Weff, g_Weff);
    cudaGetSymbolAddress((void**)&beff, g_beff);
    cudaGetSymbolAddress((void**)&Wh, g_Wh);

    const int smemProj = 3 * 128 * SA * 2;   // ~102 KB
    const int smemOut  = 2 * 128 * SA * 2;   // ~68 KB
    cudaFuncSetAttribute(proj_kernel, cudaFuncAttributeMaxDynamicSharedMemorySize, smemProj);
    cudaFuncSetAttribute(out_kernel, cudaFuncAttributeMaxDynamicSharedMemorySize, smemOut);

    build_eff_kernel<<<12, 256, 0, 0>>>(Wk, bk, Wv, bv, a_rel, m_rel, Weff, beff);
    prep_wh_kernel<<<20, 256, 0, 0>>>(Wq, Wa, Weff, Wh);

    const int gridU = (NU + 127) / 128;   // 782
    const int gridN = (NN + 127) / 128;   // 157
    const int edgeBlocks = (3 * EE + 7) / 8;

    for (int l = 0; l < NLAYER; l++) {
        const float* xinU = (l == 0) ? x_user : x1;
        const float* xinN = (l == 0) ? x_news : (x1 + (size_t)NU * CC);
        float* xout = (l == 0) ? x1 : (float*)d_out;
        size_t wl = (size_t)l * 10 * CC * CC;

        // fused user projections: q, k_r0, v_r0, k_r2, v_r2
        {
            ProjArgs pa;
            pa.X = xinU; pa.N = NU; pa.nW = 5;
            pa.W[0] = Wh + wl + 0 * CC * CC;  pa.bias[0] = bq + (l * 2 + 0) * CC;              pa.out[0] = qh;
            pa.W[1] = Wh + wl + 2 * CC * CC;  pa.bias[1] = beff + ((l * 3 + 0) * 2 + 0) * CC;  pa.out[1] = krelh;
            pa.W[2] = Wh + wl + 3 * CC * CC;  pa.bias[2] = beff + ((l * 3 + 0) * 2 + 1) * CC;  pa.out[2] = vrelh;
            pa.W[3] = Wh + wl + 6 * CC * CC;  pa.bias[3] = beff + ((l * 3 + 2) * 2 + 0) * CC;  pa.out[3] = krelh + (size_t)(NU + NN) * CC;
            pa.W[4] = Wh + wl + 7 * CC * CC;  pa.bias[4] = beff + ((l * 3 + 2) * 2 + 1) * CC;  pa.out[4] = vrelh + (size_t)(NU + NN) * CC;
            proj_kernel<<<gridU, 256, smemProj, 0>>>(pa);
        }
        // fused news projections: q, k_r1, v_r1
        {
            ProjArgs pa;
            pa.X = xinN; pa.N = NN; pa.nW = 3;
            pa.W[0] = Wh + wl + 1 * CC * CC;  pa.bias[0] = bq + (l * 2 + 1) * CC;              pa.out[0] = qh + (size_t)NU * CC;
            pa.W[1] = Wh + wl + 4 * CC * CC;  pa.bias[1] = beff + ((l * 3 + 1) * 2 + 0) * CC;  pa.out[1] = krelh + (size_t)NU * CC;
            pa.W[2] = Wh + wl + 5 * CC * CC;  pa.bias[2] = beff + ((l * 3 + 1) * 2 + 1) * CC;  pa.out[2] = vrelh + (size_t)NU * CC;
            proj_kernel<<<gridN, 256, smemProj, 0>>>(pa);
        }

        cudaMemsetAsync(aggr, 0, (size_t)NKV * CC * 4, 0);
        cudaMemsetAsync(den, 0, (size_t)3 * NU * 4 * 4, 0);

        edge_fused<<<edgeBlocks, 256, 0, 0>>>(ei0, ei1, ei2, qh, krelh, vrelh,
                                              p_rel + l * 12, den, aggr);

        // user out: combine r1 + r2
        out_kernel<<<gridU, 256, smemOut, 0>>>(
            aggr + (size_t)NN * CC, den + (size_t)1 * NU * 4,
            aggr + (size_t)(NN + NU) * CC, den + (size_t)2 * NU * 4,
            Wh + wl + 8 * CC * CC, ba + (l * 2 + 0) * CC,
            xout, NU, xinU, skip + l * 2 + 0);
        // news out: r0 only
        out_kernel<<<gridN, 256, smemOut, 0>>>(
            aggr, den,
            nullptr, nullptr,
            Wh + wl + 9 * CC * CC, ba + (l * 2 + 1) * CC,
            xout + (size_t)NU * CC, NN, xinN, skip + l * 2 + 1);
    }
}

// round 6
// speedup vs baseline: 2.1596x; 1.1092x over previous
#include <cuda_runtime.h>
#include <cuda_fp16.h>
#include <math.h>
#include <stdint.h>

#define NU 100000
#define NN 20000
#define NT 120000
#define CC 128
#define EE 250000
#define NLAYER 2
#define NKV 220000   // NU + NN + NU
#define SA 136       // smem row stride in halves (conflict-free frag loads)
#define NDST (NN + 2 * NU)   // total (relation,dst) nodes: r0=NN, r1=NU, r2=NU

// ---------------- scratch (device globals; no allocations allowed) ----------
__device__ float g_x1[NT * CC];
__device__ __half g_qh[NT * CC];
__device__ __half g_krelh[NKV * CC];
__device__ __half g_vrelh[NKV * CC];
__device__ float g_aggr[NKV * CC];     // normalized per-relation agg: r0(NN) r1(NU) r2(NU)
__device__ float g_Weff[12 * CC * CC];
__device__ float g_beff[12 * CC];
__device__ __half g_Wh[20 * CC * CC];  // fp16, transposed [n][k]
// CSR scratch
__device__ int g_cnt[NDST];
__device__ int g_off0[NN + 1];
__device__ int g_off1[NU + 1];
__device__ int g_off2[NU + 1];
__device__ int g_srt[3 * EE];

__device__ __forceinline__ float gelu_exact(float x) {
    return 0.5f * x * (1.0f + erff(x * 0.70710678118654752f));
}
__device__ __forceinline__ uint32_t smem_u32(const void* p) {
    uint32_t a;
    asm("{ .reg .u64 t; cvta.to.shared.u64 t, %1; cvt.u32.u64 %0, t; }" : "=r"(a) : "l"(p));
    return a;
}
__device__ __forceinline__ void cp16(__half* dst, const __half* src) {
    asm volatile("cp.async.cg.shared.global [%0], [%1], 16;"
                 :: "r"(smem_u32(dst)), "l"(src));
}
#define CP_COMMIT() asm volatile("cp.async.commit_group;" ::: "memory")
#define CP_WAIT0()  asm volatile("cp.async.wait_group 0;" ::: "memory")

// ---------------- effective relation weights (fp32) --------------------------
__global__ void build_eff_kernel(const float* __restrict__ Wk, const float* __restrict__ bk,
                                 const float* __restrict__ Wv, const float* __restrict__ bv,
                                 const float* __restrict__ a_rel, const float* __restrict__ m_rel,
                                 float* __restrict__ Weff, float* __restrict__ beff) {
    int b = blockIdx.x;
    int l = b / 6, rem = b % 6, r = rem >> 1, kv = rem & 1;
    int st = (r == 1) ? 1 : 0;
    const float* W   = (kv ? Wv : Wk) + (l * 2 + st) * CC * CC;
    const float* bi  = (kv ? bv : bk) + (l * 2 + st) * CC;
    const float* rel = (kv ? m_rel : a_rel) + (l * 3 + r) * 4096;
    float* out  = Weff + ((l * 3 + r) * 2 + kv) * CC * CC;
    float* bout = beff + ((l * 3 + r) * 2 + kv) * CC;

    __shared__ float rs[4096];
    for (int i = threadIdx.x; i < 4096; i += blockDim.x) rs[i] = rel[i];
    __syncthreads();

    for (int idx = threadIdx.x; idx < CC * CC; idx += blockDim.x) {
        int i = idx >> 7, j = idx & 127, h = j >> 5, e = j & 31;
        float s = 0.f;
#pragma unroll
        for (int d = 0; d < 32; d++)
            s += W[i * CC + h * 32 + d] * rs[h * 1024 + d * 32 + e];
        out[idx] = s;
    }
    if (threadIdx.x < CC) {
        int j = threadIdx.x, h = j >> 5, e = j & 31;
        float s = 0.f;
#pragma unroll
        for (int d = 0; d < 32; d++)
            s += bi[h * 32 + d] * rs[h * 1024 + d * 32 + e];
        bout[j] = s;
    }
}

// ---------------- weight prep: transpose + fp16 round ------------------------
__global__ void prep_wh_kernel(const float* __restrict__ Wq, const float* __restrict__ Wa,
                               const float* __restrict__ Weff, __half* __restrict__ Wh) {
    int b = blockIdx.x;
    int l = b / 10, m = b % 10;
    const float* src;
    if (m < 2)       src = Wq + (size_t)(l * 2 + m) * CC * CC;
    else if (m < 8)  src = Weff + (size_t)((l * 3 + (m - 2) / 2) * 2 + ((m - 2) & 1)) * CC * CC;
    else             src = Wa + (size_t)(l * 2 + (m - 8)) * CC * CC;
    __half* out = Wh + (size_t)b * CC * CC;
    for (int idx = threadIdx.x; idx < CC * CC; idx += blockDim.x) {
        int n = idx >> 7, k = idx & 127;
        out[idx] = __float2half(src[k * CC + n]);   // [n][k] = W[k][n]
    }
}

// ---------------- CSR build ---------------------------------------------------
__global__ void hist_kernel(const int* __restrict__ ei0, const int* __restrict__ ei1,
                            const int* __restrict__ ei2, int* __restrict__ cnt) {
    int t = blockIdx.x * blockDim.x + threadIdx.x;
    if (t >= 3 * EE) return;
    int r = t / EE, e = t - r * EE;
    const int* ei = (r == 0) ? ei0 : ((r == 1) ? ei1 : ei2);
    int dst = ei[EE + e];
    int cb = (r == 0) ? 0 : ((r == 1) ? NN : (NN + NU));
    atomicAdd(&cnt[cb + dst], 1);
}

// single-block-per-relation exclusive scan (block = 1024 threads)
__global__ void scan_kernel(const int* __restrict__ cnt, int* __restrict__ off0,
                            int* __restrict__ off1, int* __restrict__ off2) {
    int r = blockIdx.x;
    int n = (r == 0) ? NN : NU;
    const int* cin = cnt + ((r == 0) ? 0 : ((r == 1) ? NN : (NN + NU)));
    int* off = (r == 0) ? off0 : ((r == 1) ? off1 : off2);
    __shared__ int wsum[32];
    __shared__ int carry;
    if (threadIdx.x == 0) carry = 0;
    __syncthreads();
    int lane = threadIdx.x & 31, wid = threadIdx.x >> 5;
    for (int base = 0; base < n; base += 1024) {
        int i = base + threadIdx.x;
        int v = (i < n) ? cin[i] : 0;
        int x = v;
#pragma unroll
        for (int d = 1; d < 32; d <<= 1) {
            int y = __shfl_up_sync(0xffffffffu, x, d);
            if (lane >= d) x += y;
        }
        if (lane == 31) wsum[wid] = x;
        __syncthreads();
        if (wid == 0) {
            int s = wsum[lane];
#pragma unroll
            for (int d = 1; d < 32; d <<= 1) {
                int y = __shfl_up_sync(0xffffffffu, s, d);
                if (lane >= d) s += y;
            }
            wsum[lane] = s;
        }
        __syncthreads();
        int excl = x - v + ((wid > 0) ? wsum[wid - 1] : 0) + carry;
        if (i < n) off[i] = excl;
        int tot = wsum[31];
        __syncthreads();
        if (threadIdx.x == 0) carry += tot;
        __syncthreads();
    }
    if (threadIdx.x == 0) off[n] = carry;
}

__global__ void scatter_kernel(const int* __restrict__ ei0, const int* __restrict__ ei1,
                               const int* __restrict__ ei2,
                               const int* __restrict__ off0, const int* __restrict__ off1,
                               const int* __restrict__ off2,
                               int* __restrict__ fill, int* __restrict__ srt) {
    int t = blockIdx.x * blockDim.x + threadIdx.x;
    if (t >= 3 * EE) return;
    int r = t / EE, e = t - r * EE;
    const int* ei = (r == 0) ? ei0 : ((r == 1) ? ei1 : ei2);
    int src = ei[e], dst = ei[EE + e];
    int cb = (r == 0) ? 0 : ((r == 1) ? NN : (NN + NU));
    const int* off = (r == 0) ? off0 : ((r == 1) ? off1 : off2);
    int pos = off[dst] + atomicAdd(&fill[cb + dst], 1);
    srt[r * EE + pos] = src;
}

// ---------------- MMA compute: 128x128 tile, 8 warps (4m x 2n) ---------------
__device__ __forceinline__ void mma_tile_128(const __half* As, const __half* Bs,
                                             float acc[2][8][4], int wm, int wn,
                                             int g, int t) {
    const uint32_t* A32 = (const uint32_t*)As;
    const uint32_t* B32 = (const uint32_t*)Bs;
#pragma unroll
    for (int k0 = 0; k0 < CC; k0 += 16) {
        uint32_t a[2][4];
#pragma unroll
        for (int m = 0; m < 2; m++) {
            int ra = (wm * 32 + m * 16 + g) * (SA / 2) + (k0 >> 1) + t;
            a[m][0] = A32[ra];
            a[m][1] = A32[ra + 8 * (SA / 2)];
            a[m][2] = A32[ra + 4];
            a[m][3] = A32[ra + 8 * (SA / 2) + 4];
        }
        uint32_t b[8][2];
#pragma unroll
        for (int n = 0; n < 8; n++) {
            int rb = (wn * 64 + n * 8 + g) * (SA / 2) + (k0 >> 1) + t;
            b[n][0] = B32[rb];
            b[n][1] = B32[rb + 4];
        }
#pragma unroll
        for (int m = 0; m < 2; m++)
#pragma unroll
            for (int n = 0; n < 8; n++) {
                float* c = acc[m][n];
                asm volatile(
                    "mma.sync.aligned.m16n8k16.row.col.f32.f16.f16.f32 "
                    "{%0,%1,%2,%3}, {%4,%5,%6,%7}, {%8,%9}, {%0,%1,%2,%3};"
                    : "+f"(c[0]), "+f"(c[1]), "+f"(c[2]), "+f"(c[3])
                    : "r"(a[m][0]), "r"(a[m][1]), "r"(a[m][2]), "r"(a[m][3]),
                      "r"(b[n][0]), "r"(b[n][1]));
            }
    }
}

__device__ __forceinline__ void prefetch_B(__half* Bs, const __half* W, int tid) {
#pragma unroll
    for (int it = 0; it < 8; it++) {
        int c = tid + it * 256;
        int n = c >> 4, cc = c & 15;
        cp16(Bs + n * SA + cc * 8, W + n * CC + cc * 8);
    }
    CP_COMMIT();
}

// ---------------- merged projection kernel (user 5W + news 3W) ---------------
struct ProjArgs {
    const float* XU; const float* XN;
    int gridU;
    const __half* W[8];        // 0..4 user, 5..7 news
    const float* bias[8];
    __half* out[8];
};

__global__ __launch_bounds__(256, 2)
void proj_kernel(ProjArgs pa) {
    extern __shared__ __half smh[];
    __half* As  = smh;
    __half* Bs0 = smh + 128 * SA;
    __half* Bs1 = smh + 2 * 128 * SA;
    int tid = threadIdx.x;

    const float* X;
    int N, row0, w0, nW;
    if ((int)blockIdx.x < pa.gridU) {
        X = pa.XU; N = NU; row0 = blockIdx.x * 128; w0 = 0; nW = 5;
    } else {
        X = pa.XN; N = NN; row0 = (blockIdx.x - pa.gridU) * 128; w0 = 5; nW = 3;
    }

    prefetch_B(Bs0, pa.W[w0], tid);

    const float4* X4 = (const float4*)X;
#pragma unroll
    for (int it = 0; it < 16; it++) {
        int idx = tid + it * 256;
        int row = idx >> 5, q4 = idx & 31;
        int gr = row0 + row;
        float4 v = make_float4(0.f, 0.f, 0.f, 0.f);
        if (gr < N) v = X4[gr * 32 + q4];
        __half2 h0 = __floats2half2_rn(v.x, v.y);
        __half2 h1 = __floats2half2_rn(v.z, v.w);
        uint2 u;
        u.x = *(uint32_t*)&h0; u.y = *(uint32_t*)&h1;
        *(uint2*)(As + row * SA + q4 * 4) = u;
    }
    CP_WAIT0();
    __syncthreads();

    int wid = tid >> 5, lane = tid & 31;
    int wm = wid & 3, wn = wid >> 2;
    int g = lane >> 2, t = lane & 3;

    for (int w = 0; w < nW; w++) {
        __half* Bcur = (w & 1) ? Bs1 : Bs0;
        if (w + 1 < nW) prefetch_B((w & 1) ? Bs0 : Bs1, pa.W[w0 + w + 1], tid);

        float acc[2][8][4];
#pragma unroll
        for (int m = 0; m < 2; m++)
#pragma unroll
            for (int n = 0; n < 8; n++)
#pragma unroll
                for (int c = 0; c < 4; c++) acc[m][n][c] = 0.f;

        mma_tile_128(As, Bcur, acc, wm, wn, g, t);

        const float* bias = pa.bias[w0 + w];
        __half* out = pa.out[w0 + w];
#pragma unroll
        for (int m = 0; m < 2; m++) {
#pragma unroll
            for (int n = 0; n < 8; n++) {
                int col = wn * 64 + n * 8 + 2 * t;
                float bx = bias[col], by = bias[col + 1];
                int r0 = row0 + wm * 32 + m * 16 + g;
                if (r0 < N) {
                    __half2 o = __floats2half2_rn(acc[m][n][0] + bx, acc[m][n][1] + by);
                    *(__half2*)&out[(size_t)r0 * CC + col] = o;
                }
                int r1 = r0 + 8;
                if (r1 < N) {
                    __half2 o = __floats2half2_rn(acc[m][n][2] + bx, acc[m][n][3] + by);
                    *(__half2*)&out[(size_t)r1 * CC + col] = o;
                }
            }
        }
        if (w + 1 < nW) { CP_WAIT0(); __syncthreads(); }
    }
}

// ---------------- CSR aggregation: warp per (relation,dst) node --------------
// Softmax-normalized aggregation, all in registers; one plain store per node.
__global__ __launch_bounds__(256)
void agg_kernel(const int* __restrict__ off0, const int* __restrict__ off1,
                const int* __restrict__ off2, const int* __restrict__ srt,
                const __half* __restrict__ qh, const __half* __restrict__ krelh,
                const __half* __restrict__ vrelh,
                const float* __restrict__ prel,   // + l*12
                float* __restrict__ aggr) {
    int w = (blockIdx.x * blockDim.x + threadIdx.x) >> 5;
    int lane = threadIdx.x & 31;
    if (w >= NDST) return;
    int r, dst, qrow, kbase;
    const int* off;
    if (w < NN)            { r = 0; dst = w;            qrow = NU + dst; kbase = 0;       off = off0; }
    else if (w < NN + NU)  { r = 1; dst = w - NN;       qrow = dst;      kbase = NU;      off = off1; }
    else                   { r = 2; dst = w - NN - NU;  qrow = dst;      kbase = NU + NN; off = off2; }

    int base = off[dst];
    int deg = off[dst + 1] - base;
    int h = lane >> 3;
    float pscale = prel[r * 4 + h] * 0.17677669529663689f;

    uint2 qa = *(const uint2*)(qh + (size_t)qrow * CC + lane * 4);
    float2 q0 = __half22float2(*(__half2*)&qa.x), q1 = __half22float2(*(__half2*)&qa.y);

    float a0 = 0.f, a1 = 0.f, a2 = 0.f, a3 = 0.f, den = 0.f;
    const int* sp = srt + r * EE + base;
    for (int c = 0; c < deg; c += 32) {
        int m = min(32, deg - c);
        int si = (lane < m) ? sp[c + lane] : 0;
        for (int i = 0; i < m; i++) {
            int src = __shfl_sync(0xffffffffu, si, i);
            size_t rowo = (size_t)(kbase + src) * CC + lane * 4;
            uint2 ka = *(const uint2*)(krelh + rowo);
            uint2 va = *(const uint2*)(vrelh + rowo);
            float2 k0 = __half22float2(*(__half2*)&ka.x), k1 = __half22float2(*(__half2*)&ka.y);
            float s = q0.x * k0.x + q0.y * k0.y + q1.x * k1.x + q1.y * k1.y;
            s += __shfl_xor_sync(0xffffffffu, s, 1);
            s += __shfl_xor_sync(0xffffffffu, s, 2);
            s += __shfl_xor_sync(0xffffffffu, s, 4);
            float ex = __expf(s * pscale);
            float2 v0 = __half22float2(*(__half2*)&va.x), v1 = __half22float2(*(__half2*)&va.y);
            a0 = fmaf(ex, v0.x, a0); a1 = fmaf(ex, v0.y, a1);
            a2 = fmaf(ex, v1.x, a2); a3 = fmaf(ex, v1.y, a3);
            den += ex;
        }
    }
    float inv = 1.f / (den + 1e-16f);
    float4 o = make_float4(a0 * inv, a1 * inv, a2 * inv, a3 * inv);
    *(float4*)&aggr[(size_t)w * CC + lane * 4] = o;
}

// ---------------- merged output GEMM (user + news) ---------------------------
struct OutArgs {
    int gridU;
    const float* aggU1; const float* aggU2; const float* aggN;
    const __half* WU; const __half* WN;
    const float* biasU; const float* biasN;
    float* YU; float* YN;
    const float* xoldU; const float* xoldN;
    const float* skipU; const float* skipN;
};

__global__ __launch_bounds__(256, 2)
void out_kernel(OutArgs oa) {
    extern __shared__ __half smh[];
    __half* As = smh;
    __half* Bs = smh + 128 * SA;
    int tid = threadIdx.x;

    const float *aggA, *aggB, *bias, *xold, *skipPtr;
    const __half* W;
    float* Y;
    int N, row0;
    if ((int)blockIdx.x < oa.gridU) {
        aggA = oa.aggU1; aggB = oa.aggU2; W = oa.WU; bias = oa.biasU;
        Y = oa.YU; xold = oa.xoldU; skipPtr = oa.skipU; N = NU;
        row0 = blockIdx.x * 128;
    } else {
        aggA = oa.aggN; aggB = nullptr; W = oa.WN; bias = oa.biasN;
        Y = oa.YN; xold = oa.xoldN; skipPtr = oa.skipN; N = NN;
        row0 = (blockIdx.x - oa.gridU) * 128;
    }

    prefetch_B(Bs, W, tid);

    const float4* A4 = (const float4*)aggA;
    const float4* B4 = (const float4*)aggB;
#pragma unroll
    for (int it = 0; it < 16; it++) {
        int idx = tid + it * 256;
        int row = idx >> 5, q4 = idx & 31;
        int gr = row0 + row;
        float4 v = make_float4(0.f, 0.f, 0.f, 0.f);
        if (gr < N) {
            float4 a = A4[(size_t)gr * 32 + q4];
            v = a;
            if (aggB) {
                float4 b = B4[(size_t)gr * 32 + q4];
                v.x += b.x; v.y += b.y; v.z += b.z; v.w += b.w;
            }
            v.x = gelu_exact(v.x); v.y = gelu_exact(v.y);
            v.z = gelu_exact(v.z); v.w = gelu_exact(v.w);
        }
        __half2 h0 = __floats2half2_rn(v.x, v.y);
        __half2 h1 = __floats2half2_rn(v.z, v.w);
        uint2 u;
        u.x = *(uint32_t*)&h0; u.y = *(uint32_t*)&h1;
        *(uint2*)(As + row * SA + q4 * 4) = u;
    }
    CP_WAIT0();
    __syncthreads();

    int wid = tid >> 5, lane = tid & 31;
    int wm = wid & 3, wn = wid >> 2;
    int g = lane >> 2, t = lane & 3;

    float acc[2][8][4];
#pragma unroll
    for (int m = 0; m < 2; m++)
#pragma unroll
        for (int n = 0; n < 8; n++)
#pragma unroll
            for (int c = 0; c < 4; c++) acc[m][n][c] = 0.f;

    mma_tile_128(As, Bs, acc, wm, wn, g, t);

    float s = *skipPtr;
    float aS = 1.f / (1.f + expf(-s));
    float bS = 1.f - aS;
#pragma unroll
    for (int m = 0; m < 2; m++) {
#pragma unroll
        for (int n = 0; n < 8; n++) {
            int col = wn * 64 + n * 8 + 2 * t;
            float bx = bias[col], by = bias[col + 1];
            int r0 = row0 + wm * 32 + m * 16 + g;
            if (r0 < N) {
                float2 xo = *(const float2*)&xold[(size_t)r0 * CC + col];
                float2 o;
                o.x = fmaxf(fmaf(aS, acc[m][n][0] + bx, bS * xo.x), 0.f);
                o.y = fmaxf(fmaf(aS, acc[m][n][1] + by, bS * xo.y), 0.f);
                *(float2*)&Y[(size_t)r0 * CC + col] = o;
            }
            int r1 = r0 + 8;
            if (r1 < N) {
                float2 xo = *(const float2*)&xold[(size_t)r1 * CC + col];
                float2 o;
                o.x = fmaxf(fmaf(aS, acc[m][n][2] + bx, bS * xo.x), 0.f);
                o.y = fmaxf(fmaf(aS, acc[m][n][3] + by, bS * xo.y), 0.f);
                *(float2*)&Y[(size_t)r1 * CC + col] = o;
            }
        }
    }
}

// ---------------- host orchestration ----------------------------------------
extern "C" void kernel_launch(void* const* d_in, const int* in_sizes, int n_in,
                              void* d_out, int out_size) {
    const float* x_user = (const float*)d_in[0];
    const float* x_news = (const float*)d_in[1];
    const int* ei0 = (const int*)d_in[2];
    const int* ei1 = (const int*)d_in[3];
    const int* ei2 = (const int*)d_in[4];
    const float* Wk = (const float*)d_in[5];
    const float* bk = (const float*)d_in[6];
    const float* Wq = (const float*)d_in[7];
    const float* bq = (const float*)d_in[8];
    const float* Wv = (const float*)d_in[9];
    const float* bv = (const float*)d_in[10];
    const float* Wa = (const float*)d_in[11];
    const float* ba = (const float*)d_in[12];
    const float* skip = (const float*)d_in[13];
    const float* a_rel = (const float*)d_in[14];
    const float* m_rel = (const float*)d_in[15];
    const float* p_rel = (const float*)d_in[16];

    float *x1, *aggr, *Weff, *beff;
    __half *qh, *krelh, *vrelh, *Wh;
    int *cnt, *off0, *off1, *off2, *srt;
    cudaGetSymbolAddress((void**)&x1, g_x1);
    cudaGetSymbolAddress((void**)&aggr, g_aggr);
    cudaGetSymbolAddress((void**)&qh, g_qh);
    cudaGetSymbolAddress((void**)&krelh, g_krelh);
    cudaGetSymbolAddress((void**)&vrelh, g_vrelh);
    cudaGetSymbolAddress((void**)&Weff, g_Weff);
    cudaGetSymbolAddress((void**)&beff, g_beff);
    cudaGetSymbolAddress((void**)&Wh, g_Wh);
    cudaGetSymbolAddress((void**)&cnt, g_cnt);
    cudaGetSymbolAddress((void**)&off0, g_off0);
    cudaGetSymbolAddress((void**)&off1, g_off1);
    cudaGetSymbolAddress((void**)&off2, g_off2);
    cudaGetSymbolAddress((void**)&srt, g_srt);

    const int smemProj = 3 * 128 * SA * 2;   // ~102 KB
    const int smemOut  = 2 * 128 * SA * 2;   // ~68 KB
    cudaFuncSetAttribute(proj_kernel, cudaFuncAttributeMaxDynamicSharedMemorySize, smemProj);
    cudaFuncSetAttribute(out_kernel, cudaFuncAttributeMaxDynamicSharedMemorySize, smemOut);

    // setup: effective weights + fp16 transposed weights
    build_eff_kernel<<<12, 256, 0, 0>>>(Wk, bk, Wv, bv, a_rel, m_rel, Weff, beff);
    prep_wh_kernel<<<20, 256, 0, 0>>>(Wq, Wa, Weff, Wh);

    // CSR build (edges constant across layers)
    const int eb = (3 * EE + 255) / 256;
    cudaMemsetAsync(cnt, 0, NDST * sizeof(int), 0);
    hist_kernel<<<eb, 256, 0, 0>>>(ei0, ei1, ei2, cnt);
    scan_kernel<<<3, 1024, 0, 0>>>(cnt, off0, off1, off2);
    cudaMemsetAsync(cnt, 0, NDST * sizeof(int), 0);
    scatter_kernel<<<eb, 256, 0, 0>>>(ei0, ei1, ei2, off0, off1, off2, cnt, srt);

    const int gridU = (NU + 127) / 128;   // 782
    const int gridN = (NN + 127) / 128;   // 157
    const int aggBlocks = (NDST + 7) / 8;

    for (int l = 0; l < NLAYER; l++) {
        const float* xinU = (l == 0) ? x_user : x1;
        const float* xinN = (l == 0) ? x_news : (x1 + (size_t)NU * CC);
        float* xout = (l == 0) ? x1 : (float*)d_out;
        size_t wl = (size_t)l * 10 * CC * CC;

        ProjArgs pa;
        pa.XU = xinU; pa.XN = xinN; pa.gridU = gridU;
        pa.W[0] = Wh + wl + 0 * CC * CC;  pa.bias[0] = bq + (l * 2 + 0) * CC;              pa.out[0] = qh;
        pa.W[1] = Wh + wl + 2 * CC * CC;  pa.bias[1] = beff + ((l * 3 + 0) * 2 + 0) * CC;  pa.out[1] = krelh;
        pa.W[2] = Wh + wl + 3 * CC * CC;  pa.bias[2] = beff + ((l * 3 + 0) * 2 + 1) * CC;  pa.out[2] = vrelh;
        pa.W[3] = Wh + wl + 6 * CC * CC;  pa.bias[3] = beff + ((l * 3 + 2) * 2 + 0) * CC;  pa.out[3] = krelh + (size_t)(NU + NN) * CC;
        pa.W[4] = Wh + wl + 7 * CC * CC;  pa.bias[4] = beff + ((l * 3 + 2) * 2 + 1) * CC;  pa.out[4] = vrelh + (size_t)(NU + NN) * CC;
        pa.W[5] = Wh + wl + 1 * CC * CC;  pa.bias[5] = bq + (l * 2 + 1) * CC;              pa.out[5] = qh + (size_t)NU * CC;
        pa.W[6] = Wh + wl + 4 * CC * CC;  pa.bias[6] = beff + ((l * 3 + 1) * 2 + 0) * CC;  pa.out[6] = krelh + (size_t)NU * CC;
        pa.W[7] = Wh + wl + 5 * CC * CC;  pa.bias[7] = beff + ((l * 3 + 1) * 2 + 1) * CC;  pa.out[7] = vrelh + (size_t)NU * CC;
        proj_kernel<<<gridU + gridN, 256, smemProj, 0>>>(pa);

        agg_kernel<<<aggBlocks, 256, 0, 0>>>(off0, off1, off2, srt,
                                             qh, krelh, vrelh, p_rel + l * 12, aggr);

        OutArgs oa;
        oa.gridU = gridU;
        oa.aggU1 = aggr + (size_t)NN * CC;
        oa.aggU2 = aggr + (size_t)(NN + NU) * CC;
        oa.aggN  = aggr;
        oa.WU = Wh + wl + 8 * CC * CC;  oa.WN = Wh + wl + 9 * CC * CC;
        oa.biasU = ba + (l * 2 + 0) * CC;  oa.biasN = ba + (l * 2 + 1) * CC;
        oa.YU = xout;  oa.YN = xout + (size_t)NU * CC;
        oa.xoldU = xinU;  oa.xoldN = xinN;
        oa.skipU = skip + l * 2 + 0;  oa.skipN = skip + l * 2 + 1;
        out_kernel<<<gridU + gridN, 256, smemOut, 0>>>(oa);
    }
}

// round 7
// speedup vs baseline: 2.4776x; 1.1472x over previous
#include <cuda_runtime.h>
#include <cuda_fp16.h>
#include <math.h>
#include <stdint.h>

#define NU 100000
#define NN 20000
#define NT 120000
#define CC 128
#define EE 250000
#define NLAYER 2
#define NKV 220000   // NU + NN + NU
#define SA 136       // smem row stride in halves (conflict-free frag loads)
#define NDST (NN + 2 * NU)   // (relation,dst) nodes: r0=NN, r1=NU, r2=NU
#define SCAN_BLK 4096
#define SCAN_NB ((NDST + SCAN_BLK - 1) / SCAN_BLK)

// ---------------- scratch (device globals; no allocations allowed) ----------
__device__ float g_x1[NT * CC];
__device__ __half g_qh[NT * CC];
__device__ __half g_krelh[NKV * CC];
__device__ __half g_vrelh[NKV * CC];
__device__ float g_aggr[NKV * CC];     // normalized per-relation agg: r0(NN) r1(NU) r2(NU)
__device__ float g_Weff[12 * CC * CC];
__device__ float g_beff[12 * CC];
__device__ __half g_Wh[20 * CC * CC];  // fp16, transposed [n][k]
// CSR scratch
__device__ int g_cnt[NDST];
__device__ int g_offAll[NDST + 1];
__device__ int g_bsum[SCAN_NB];
__device__ int g_srt[3 * EE];

__device__ __forceinline__ float gelu_exact(float x) {
    return 0.5f * x * (1.0f + erff(x * 0.70710678118654752f));
}
__device__ __forceinline__ uint32_t smem_u32(const void* p) {
    uint32_t a;
    asm("{ .reg .u64 t; cvta.to.shared.u64 t, %1; cvt.u32.u64 %0, t; }" : "=r"(a) : "l"(p));
    return a;
}
__device__ __forceinline__ void cp16(__half* dst, const __half* src) {
    asm volatile("cp.async.cg.shared.global [%0], [%1], 16;"
                 :: "r"(smem_u32(dst)), "l"(src));
}
#define CP_COMMIT() asm volatile("cp.async.commit_group;" ::: "memory")
#define CP_WAIT0()  asm volatile("cp.async.wait_group 0;" ::: "memory")

// ---------------- effective relation weights (fp32) --------------------------
__global__ void build_eff_kernel(const float* __restrict__ Wk, const float* __restrict__ bk,
                                 const float* __restrict__ Wv, const float* __restrict__ bv,
                                 const float* __restrict__ a_rel, const float* __restrict__ m_rel,
                                 float* __restrict__ Weff, float* __restrict__ beff) {
    int b = blockIdx.x;
    int l = b / 6, rem = b % 6, r = rem >> 1, kv = rem & 1;
    int st = (r == 1) ? 1 : 0;
    const float* W   = (kv ? Wv : Wk) + (l * 2 + st) * CC * CC;
    const float* bi  = (kv ? bv : bk) + (l * 2 + st) * CC;
    const float* rel = (kv ? m_rel : a_rel) + (l * 3 + r) * 4096;
    float* out  = Weff + ((l * 3 + r) * 2 + kv) * CC * CC;
    float* bout = beff + ((l * 3 + r) * 2 + kv) * CC;

    __shared__ float rs[4096];
    for (int i = threadIdx.x; i < 4096; i += blockDim.x) rs[i] = rel[i];
    __syncthreads();

    for (int idx = threadIdx.x; idx < CC * CC; idx += blockDim.x) {
        int i = idx >> 7, j = idx & 127, h = j >> 5, e = j & 31;
        float s = 0.f;
#pragma unroll
        for (int d = 0; d < 32; d++)
            s += W[i * CC + h * 32 + d] * rs[h * 1024 + d * 32 + e];
        out[idx] = s;
    }
    if (threadIdx.x < CC) {
        int j = threadIdx.x, h = j >> 5, e = j & 31;
        float s = 0.f;
#pragma unroll
        for (int d = 0; d < 32; d++)
            s += bi[h * 32 + d] * rs[h * 1024 + d * 32 + e];
        bout[j] = s;
    }
}

// ---------------- weight prep: transpose + fp16 round ------------------------
__global__ void prep_wh_kernel(const float* __restrict__ Wq, const float* __restrict__ Wa,
                               const float* __restrict__ Weff, __half* __restrict__ Wh) {
    int b = blockIdx.x;
    int l = b / 10, m = b % 10;
    const float* src;
    if (m < 2)       src = Wq + (size_t)(l * 2 + m) * CC * CC;
    else if (m < 8)  src = Weff + (size_t)((l * 3 + (m - 2) / 2) * 2 + ((m - 2) & 1)) * CC * CC;
    else             src = Wa + (size_t)(l * 2 + (m - 8)) * CC * CC;
    __half* out = Wh + (size_t)b * CC * CC;
    for (int idx = threadIdx.x; idx < CC * CC; idx += blockDim.x) {
        int n = idx >> 7, k = idx & 127;
        out[idx] = __float2half(src[k * CC + n]);   // [n][k] = W[k][n]
    }
}

// ---------------- CSR build ---------------------------------------------------
__global__ void hist_kernel(const int* __restrict__ ei0, const int* __restrict__ ei1,
                            const int* __restrict__ ei2, int* __restrict__ cnt) {
    int t = blockIdx.x * blockDim.x + threadIdx.x;
    if (t >= 3 * EE) return;
    int r = t / EE, e = t - r * EE;
    const int* ei = (r == 0) ? ei0 : ((r == 1) ? ei1 : ei2);
    int dst = ei[EE + e];
    int cb = (r == 0) ? 0 : ((r == 1) ? NN : (NN + NU));
    atomicAdd(&cnt[cb + dst], 1);
}

// phase 1: block-local exclusive scan (4 elems/thread), emit block sums
__global__ void scan1_kernel(const int* __restrict__ cnt, int* __restrict__ offAll,
                             int* __restrict__ bsum) {
    __shared__ int wsum[32];
    int lane = threadIdx.x & 31, wid = threadIdx.x >> 5;
    int base = blockIdx.x * SCAN_BLK + threadIdx.x * 4;
    int v0 = (base + 0 < NDST) ? cnt[base + 0] : 0;
    int v1 = (base + 1 < NDST) ? cnt[base + 1] : 0;
    int v2 = (base + 2 < NDST) ? cnt[base + 2] : 0;
    int v3 = (base + 3 < NDST) ? cnt[base + 3] : 0;
    int tsum = v0 + v1 + v2 + v3;
    int x = tsum;
#pragma unroll
    for (int d = 1; d < 32; d <<= 1) {
        int y = __shfl_up_sync(0xffffffffu, x, d);
        if (lane >= d) x += y;
    }
    if (lane == 31) wsum[wid] = x;
    __syncthreads();
    if (wid == 0) {
        int s = wsum[lane];
#pragma unroll
        for (int d = 1; d < 32; d <<= 1) {
            int y = __shfl_up_sync(0xffffffffu, s, d);
            if (lane >= d) s += y;
        }
        wsum[lane] = s;
    }
    __syncthreads();
    int run = x - tsum + ((wid > 0) ? wsum[wid - 1] : 0);
    if (base + 0 < NDST) offAll[base + 0] = run;  run += v0;
    if (base + 1 < NDST) offAll[base + 1] = run;  run += v1;
    if (base + 2 < NDST) offAll[base + 2] = run;  run += v2;
    if (base + 3 < NDST) offAll[base + 3] = run;
    if (threadIdx.x == 0) bsum[blockIdx.x] = wsum[31];
}

// phase 2: exclusive scan of block sums (one block)
__global__ void scan2_kernel(int* __restrict__ bsum) {
    int lane = threadIdx.x;   // blockDim = 64 >= SCAN_NB
    int v = (lane < SCAN_NB) ? bsum[lane] : 0;
    int x = v;
#pragma unroll
    for (int d = 1; d < 64; d <<= 1) {
        int y = __shfl_up_sync(0xffffffffu, x, d);   // 64>32: use two-warp path below
        if ((lane & 31) >= d) x += y;
    }
    // cross-warp fix for 64 threads
    __shared__ int w0tot;
    if (lane == 31) w0tot = x;
    __syncthreads();
    if (lane >= 32) x += w0tot;
    if (lane < SCAN_NB) bsum[lane] = x - v;
}

// phase 3: add block offsets; set sentinel
__global__ void scan3_kernel(int* __restrict__ offAll, const int* __restrict__ bsum) {
    int base = blockIdx.x * SCAN_BLK + threadIdx.x * 4;
    int add = bsum[blockIdx.x];
#pragma unroll
    for (int j = 0; j < 4; j++)
        if (base + j < NDST) offAll[base + j] += add;
    if (blockIdx.x == 0 && threadIdx.x == 0) offAll[NDST] = 3 * EE;
}

__global__ void scatter_kernel(const int* __restrict__ ei0, const int* __restrict__ ei1,
                               const int* __restrict__ ei2,
                               const int* __restrict__ offAll,
                               int* __restrict__ fill, int* __restrict__ srt) {
    int t = blockIdx.x * blockDim.x + threadIdx.x;
    if (t >= 3 * EE) return;
    int r = t / EE, e = t - r * EE;
    const int* ei = (r == 0) ? ei0 : ((r == 1) ? ei1 : ei2);
    int src = ei[e], dst = ei[EE + e];
    int cb = (r == 0) ? 0 : ((r == 1) ? NN : (NN + NU));
    int pos = offAll[cb + dst] + atomicAdd(&fill[cb + dst], 1);
    srt[pos] = src;
}

// ---------------- MMA compute: 128x128 tile, 8 warps (4m x 2n) ---------------
__device__ __forceinline__ void mma_tile_128(const __half* As, const __half* Bs,
                                             float acc[2][8][4], int wm, int wn,
                                             int g, int t) {
    const uint32_t* A32 = (const uint32_t*)As;
    const uint32_t* B32 = (const uint32_t*)Bs;
#pragma unroll
    for (int k0 = 0; k0 < CC; k0 += 16) {
        uint32_t a[2][4];
#pragma unroll
        for (int m = 0; m < 2; m++) {
            int ra = (wm * 32 + m * 16 + g) * (SA / 2) + (k0 >> 1) + t;
            a[m][0] = A32[ra];
            a[m][1] = A32[ra + 8 * (SA / 2)];
            a[m][2] = A32[ra + 4];
            a[m][3] = A32[ra + 8 * (SA / 2) + 4];
        }
        uint32_t b[8][2];
#pragma unroll
        for (int n = 0; n < 8; n++) {
            int rb = (wn * 64 + n * 8 + g) * (SA / 2) + (k0 >> 1) + t;
            b[n][0] = B32[rb];
            b[n][1] = B32[rb + 4];
        }
#pragma unroll
        for (int m = 0; m < 2; m++)
#pragma unroll
            for (int n = 0; n < 8; n++) {
                float* c = acc[m][n];
                asm volatile(
                    "mma.sync.aligned.m16n8k16.row.col.f32.f16.f16.f32 "
                    "{%0,%1,%2,%3}, {%4,%5,%6,%7}, {%8,%9}, {%0,%1,%2,%3};"
                    : "+f"(c[0]), "+f"(c[1]), "+f"(c[2]), "+f"(c[3])
                    : "r"(a[m][0]), "r"(a[m][1]), "r"(a[m][2]), "r"(a[m][3]),
                      "r"(b[n][0]), "r"(b[n][1]));
            }
    }
}

__device__ __forceinline__ void prefetch_B(__half* Bs, const __half* W, int tid) {
#pragma unroll
    for (int it = 0; it < 8; it++) {
        int c = tid + it * 256;
        int n = c >> 4, cc = c & 15;
        cp16(Bs + n * SA + cc * 8, W + n * CC + cc * 8);
    }
    CP_COMMIT();
}

// ---------------- merged projection kernel (user 5W + news 3W) ---------------
struct ProjArgs {
    const float* XU; const float* XN;
    int gridU;
    const __half* W[8];
    const float* bias[8];
    __half* out[8];
};

__global__ __launch_bounds__(256, 2)
void proj_kernel(ProjArgs pa) {
    extern __shared__ __half smh[];
    __half* As  = smh;
    __half* Bs0 = smh + 128 * SA;
    __half* Bs1 = smh + 2 * 128 * SA;
    int tid = threadIdx.x;

    const float* X;
    int N, row0, w0, nW;
    if ((int)blockIdx.x < pa.gridU) {
        X = pa.XU; N = NU; row0 = blockIdx.x * 128; w0 = 0; nW = 5;
    } else {
        X = pa.XN; N = NN; row0 = (blockIdx.x - pa.gridU) * 128; w0 = 5; nW = 3;
    }

    prefetch_B(Bs0, pa.W[w0], tid);

    const float4* X4 = (const float4*)X;
#pragma unroll
    for (int it = 0; it < 16; it++) {
        int idx = tid + it * 256;
        int row = idx >> 5, q4 = idx & 31;
        int gr = row0 + row;
        float4 v = make_float4(0.f, 0.f, 0.f, 0.f);
        if (gr < N) v = X4[gr * 32 + q4];
        __half2 h0 = __floats2half2_rn(v.x, v.y);
        __half2 h1 = __floats2half2_rn(v.z, v.w);
        uint2 u;
        u.x = *(uint32_t*)&h0; u.y = *(uint32_t*)&h1;
        *(uint2*)(As + row * SA + q4 * 4) = u;
    }
    CP_WAIT0();
    __syncthreads();

    int wid = tid >> 5, lane = tid & 31;
    int wm = wid & 3, wn = wid >> 2;
    int g = lane >> 2, t = lane & 3;

    for (int w = 0; w < nW; w++) {
        __half* Bcur = (w & 1) ? Bs1 : Bs0;
        if (w + 1 < nW) prefetch_B((w & 1) ? Bs0 : Bs1, pa.W[w0 + w + 1], tid);

        float acc[2][8][4];
#pragma unroll
        for (int m = 0; m < 2; m++)
#pragma unroll
            for (int n = 0; n < 8; n++)
#pragma unroll
                for (int c = 0; c < 4; c++) acc[m][n][c] = 0.f;

        mma_tile_128(As, Bcur, acc, wm, wn, g, t);

        const float* bias = pa.bias[w0 + w];
        __half* out = pa.out[w0 + w];
#pragma unroll
        for (int m = 0; m < 2; m++) {
#pragma unroll
            for (int n = 0; n < 8; n++) {
                int col = wn * 64 + n * 8 + 2 * t;
                float bx = bias[col], by = bias[col + 1];
                int r0 = row0 + wm * 32 + m * 16 + g;
                if (r0 < N) {
                    __half2 o = __floats2half2_rn(acc[m][n][0] + bx, acc[m][n][1] + by);
                    *(__half2*)&out[(size_t)r0 * CC + col] = o;
                }
                int r1 = r0 + 8;
                if (r1 < N) {
                    __half2 o = __floats2half2_rn(acc[m][n][2] + bx, acc[m][n][3] + by);
                    *(__half2*)&out[(size_t)r1 * CC + col] = o;
                }
            }
        }
        if (w + 1 < nW) { CP_WAIT0(); __syncthreads(); }
    }
}

// ---------------- CSR aggregation: warp per (relation,dst) node --------------
__global__ __launch_bounds__(256)
void agg_kernel(const int* __restrict__ offAll, const int* __restrict__ srt,
                const __half* __restrict__ qh, const __half* __restrict__ krelh,
                const __half* __restrict__ vrelh,
                const float* __restrict__ prel,   // + l*12
                float* __restrict__ aggr) {
    int w = (blockIdx.x * blockDim.x + threadIdx.x) >> 5;
    int lane = threadIdx.x & 31;
    if (w >= NDST) return;
    int r, qrow, kbase;
    if (w < NN)            { r = 0; qrow = NU + w;           kbase = 0;       }
    else if (w < NN + NU)  { r = 1; qrow = w - NN;           kbase = NU;      }
    else                   { r = 2; qrow = w - NN - NU;      kbase = NU + NN; }

    int base = offAll[w];
    int deg = offAll[w + 1] - base;
    int h = lane >> 3;
    float pscale = prel[r * 4 + h] * 0.17677669529663689f;

    uint2 qa = *(const uint2*)(qh + (size_t)qrow * CC + lane * 4);
    float2 q0 = __half22float2(*(__half2*)&qa.x), q1 = __half22float2(*(__half2*)&qa.y);

    float a0 = 0.f, a1 = 0.f, a2 = 0.f, a3 = 0.f, den = 0.f;
    const int* sp = srt + base;
    for (int c = 0; c < deg; c += 32) {
        int m = min(32, deg - c);
        int si = (lane < m) ? sp[c + lane] : 0;
        int i = 0;
        for (; i + 1 < m; i += 2) {
            int s0 = __shfl_sync(0xffffffffu, si, i);
            int s1 = __shfl_sync(0xffffffffu, si, i + 1);
            size_t ro0 = (size_t)(kbase + s0) * CC + lane * 4;
            size_t ro1 = (size_t)(kbase + s1) * CC + lane * 4;
            uint2 ka0 = *(const uint2*)(krelh + ro0);
            uint2 va0 = *(const uint2*)(vrelh + ro0);
            uint2 ka1 = *(const uint2*)(krelh + ro1);
            uint2 va1 = *(const uint2*)(vrelh + ro1);
            float2 k00 = __half22float2(*(__half2*)&ka0.x), k01 = __half22float2(*(__half2*)&ka0.y);
            float2 k10 = __half22float2(*(__half2*)&ka1.x), k11 = __half22float2(*(__half2*)&ka1.y);
            float sA = q0.x * k00.x + q0.y * k00.y + q1.x * k01.x + q1.y * k01.y;
            float sB = q0.x * k10.x + q0.y * k10.y + q1.x * k11.x + q1.y * k11.y;
            sA += __shfl_xor_sync(0xffffffffu, sA, 1);
            sB += __shfl_xor_sync(0xffffffffu, sB, 1);
            sA += __shfl_xor_sync(0xffffffffu, sA, 2);
            sB += __shfl_xor_sync(0xffffffffu, sB, 2);
            sA += __shfl_xor_sync(0xffffffffu, sA, 4);
            sB += __shfl_xor_sync(0xffffffffu, sB, 4);
            float exA = __expf(sA * pscale);
            float exB = __expf(sB * pscale);
            float2 v00 = __half22float2(*(__half2*)&va0.x), v01 = __half22float2(*(__half2*)&va0.y);
            float2 v10 = __half22float2(*(__half2*)&va1.x), v11 = __half22float2(*(__half2*)&va1.y);
            a0 = fmaf(exA, v00.x, fmaf(exB, v10.x, a0));
            a1 = fmaf(exA, v00.y, fmaf(exB, v10.y, a1));
            a2 = fmaf(exA, v01.x, fmaf(exB, v11.x, a2));
            a3 = fmaf(exA, v01.y, fmaf(exB, v11.y, a3));
            den += exA + exB;
        }
        if (i < m) {
            int s0 = __shfl_sync(0xffffffffu, si, i);
            size_t ro0 = (size_t)(kbase + s0) * CC + lane * 4;
            uint2 ka0 = *(const uint2*)(krelh + ro0);
            uint2 va0 = *(const uint2*)(vrelh + ro0);
            float2 k00 = __half22float2(*(__half2*)&ka0.x), k01 = __half22float2(*(__half2*)&ka0.y);
            float sA = q0.x * k00.x + q0.y * k00.y + q1.x * k01.x + q1.y * k01.y;
            sA += __shfl_xor_sync(0xffffffffu, sA, 1);
            sA += __shfl_xor_sync(0xffffffffu, sA, 2);
            sA += __shfl_xor_sync(0xffffffffu, sA, 4);
            float exA = __expf(sA * pscale);
            float2 v00 = __half22float2(*(__half2*)&va0.x), v01 = __half22float2(*(__half2*)&va0.y);
            a0 = fmaf(exA, v00.x, a0);
            a1 = fmaf(exA, v00.y, a1);
            a2 = fmaf(exA, v01.x, a2);
            a3 = fmaf(exA, v01.y, a3);
            den += exA;
        }
    }
    float inv = 1.f / (den + 1e-16f);
    float4 o = make_float4(a0 * inv, a1 * inv, a2 * inv, a3 * inv);
    *(float4*)&aggr[(size_t)w * CC + lane * 4] = o;
}

// ---------------- merged output GEMM (user + news) ---------------------------
struct OutArgs {
    int gridU;
    const float* aggU1; const float* aggU2; const float* aggN;
    const __half* WU; const __half* WN;
    const float* biasU; const float* biasN;
    float* YU; float* YN;
    const float* xoldU; const float* xoldN;
    const float* skipU; const float* skipN;
};

__global__ __launch_bounds__(256, 2)
void out_kernel(OutArgs oa) {
    extern __shared__ __half smh[];
    __half* As = smh;
    __half* Bs = smh + 128 * SA;
    int tid = threadIdx.x;

    const float *aggA, *aggB, *bias, *xold, *skipPtr;
    const __half* W;
    float* Y;
    int N, row0;
    if ((int)blockIdx.x < oa.gridU) {
        aggA = oa.aggU1; aggB = oa.aggU2; W = oa.WU; bias = oa.biasU;
        Y = oa.YU; xold = oa.xoldU; skipPtr = oa.skipU; N = NU;
        row0 = blockIdx.x * 128;
    } else {
        aggA = oa.aggN; aggB = nullptr; W = oa.WN; bias = oa.biasN;
        Y = oa.YN; xold = oa.xoldN; skipPtr = oa.skipN; N = NN;
        row0 = (blockIdx.x - oa.gridU) * 128;
    }

    prefetch_B(Bs, W, tid);

    const float4* A4 = (const float4*)aggA;
    const float4* B4 = (const float4*)aggB;
#pragma unroll
    for (int it = 0; it < 16; it++) {
        int idx = tid + it * 256;
        int row = idx >> 5, q4 = idx & 31;
        int gr = row0 + row;
        float4 v = make_float4(0.f, 0.f, 0.f, 0.f);
        if (gr < N) {
            float4 a = A4[(size_t)gr * 32 + q4];
            v = a;
            if (aggB) {
                float4 b = B4[(size_t)gr * 32 + q4];
                v.x += b.x; v.y += b.y; v.z += b.z; v.w += b.w;
            }
            v.x = gelu_exact(v.x); v.y = gelu_exact(v.y);
            v.z = gelu_exact(v.z); v.w = gelu_exact(v.w);
        }
        __half2 h0 = __floats2half2_rn(v.x, v.y);
        __half2 h1 = __floats2half2_rn(v.z, v.w);
        uint2 u;
        u.x = *(uint32_t*)&h0; u.y = *(uint32_t*)&h1;
        *(uint2*)(As + row * SA + q4 * 4) = u;
    }
    CP_WAIT0();
    __syncthreads();

    int wid = tid >> 5, lane = tid & 31;
    int wm = wid & 3, wn = wid >> 2;
    int g = lane >> 2, t = lane & 3;

    float acc[2][8][4];
#pragma unroll
    for (int m = 0; m < 2; m++)
#pragma unroll
        for (int n = 0; n < 8; n++)
#pragma unroll
            for (int c = 0; c < 4; c++) acc[m][n][c] = 0.f;

    mma_tile_128(As, Bs, acc, wm, wn, g, t);

    float s = *skipPtr;
    float aS = 1.f / (1.f + expf(-s));
    float bS = 1.f - aS;
#pragma unroll
    for (int m = 0; m < 2; m++) {
#pragma unroll
        for (int n = 0; n < 8; n++) {
            int col = wn * 64 + n * 8 + 2 * t;
            float bx = bias[col], by = bias[col + 1];
            int r0 = row0 + wm * 32 + m * 16 + g;
            if (r0 < N) {
                float2 xo = *(const float2*)&xold[(size_t)r0 * CC + col];
                float2 o;
                o.x = fmaxf(fmaf(aS, acc[m][n][0] + bx, bS * xo.x), 0.f);
                o.y = fmaxf(fmaf(aS, acc[m][n][1] + by, bS * xo.y), 0.f);
                *(float2*)&Y[(size_t)r0 * CC + col] = o;
            }
            int r1 = r0 + 8;
            if (r1 < N) {
                float2 xo = *(const float2*)&xold[(size_t)r1 * CC + col];
                float2 o;
                o.x = fmaxf(fmaf(aS, acc[m][n][2] + bx, bS * xo.x), 0.f);
                o.y = fmaxf(fmaf(aS, acc[m][n][3] + by, bS * xo.y), 0.f);
                *(float2*)&Y[(size_t)r1 * CC + col] = o;
            }
        }
    }
}

// ---------------- host orchestration ----------------------------------------
extern "C" void kernel_launch(void* const* d_in, const int* in_sizes, int n_in,
                              void* d_out, int out_size) {
    const float* x_user = (const float*)d_in[0];
    const float* x_news = (const float*)d_in[1];
    const int* ei0 = (const int*)d_in[2];
    const int* ei1 = (const int*)d_in[3];
    const int* ei2 = (const int*)d_in[4];
    const float* Wk = (const float*)d_in[5];
    const float* bk = (const float*)d_in[6];
    const float* Wq = (const float*)d_in[7];
    const float* bq = (const float*)d_in[8];
    const float* Wv = (const float*)d_in[9];
    const float* bv = (const float*)d_in[10];
    const float* Wa = (const float*)d_in[11];
    const float* ba = (const float*)d_in[12];
    const float* skip = (const float*)d_in[13];
    const float* a_rel = (const float*)d_in[14];
    const float* m_rel = (const float*)d_in[15];
    const float* p_rel = (const float*)d_in[16];

    float *x1, *aggr, *Weff, *beff;
    __half *qh, *krelh, *vrelh, *Wh;
    int *cnt, *offAll, *bsum, *srt;
    cudaGetSymbolAddress((void**)&x1, g_x1);
    cudaGetSymbolAddress((void**)&aggr, g_aggr);
    cudaGetSymbolAddress((void**)&qh, g_qh);
    cudaGetSymbolAddress((void**)&krelh, g_krelh);
    cudaGetSymbolAddress((void**)&vrelh, g_vrelh);
    cudaGetSymbolAddress((void**)&Weff, g_Weff);
    cudaGetSymbolAddress((void**)&beff, g_beff);
    cudaGetSymbolAddress((void**)&Wh, g_Wh);
    cudaGetSymbolAddress((void**)&cnt, g_cnt);
    cudaGetSymbolAddress((void**)&offAll, g_offAll);
    cudaGetSymbolAddress((void**)&bsum, g_bsum);
    cudaGetSymbolAddress((void**)&srt, g_srt);

    const int smemProj = 3 * 128 * SA * 2;
    const int smemOut  = 2 * 128 * SA * 2;
    cudaFuncSetAttribute(proj_kernel, cudaFuncAttributeMaxDynamicSharedMemorySize, smemProj);
    cudaFuncSetAttribute(out_kernel, cudaFuncAttributeMaxDynamicSharedMemorySize, smemOut);

    build_eff_kernel<<<12, 256, 0, 0>>>(Wk, bk, Wv, bv, a_rel, m_rel, Weff, beff);
    prep_wh_kernel<<<20, 256, 0, 0>>>(Wq, Wa, Weff, Wh);

    // CSR build (edges constant across layers)
    const int eb = (3 * EE + 255) / 256;
    cudaMemsetAsync(cnt, 0, NDST * sizeof(int), 0);
    hist_kernel<<<eb, 256, 0, 0>>>(ei0, ei1, ei2, cnt);
    scan1_kernel<<<SCAN_NB, 1024, 0, 0>>>(cnt, offAll, bsum);
    scan2_kernel<<<1, 64, 0, 0>>>(bsum);
    scan3_kernel<<<SCAN_NB, 1024, 0, 0>>>(offAll, bsum);
    cudaMemsetAsync(cnt, 0, NDST * sizeof(int), 0);
    scatter_kernel<<<eb, 256, 0, 0>>>(ei0, ei1, ei2, offAll, cnt, srt);

    const int gridU = (NU + 127) / 128;
    const int gridN = (NN + 127) / 128;
    const int aggBlocks = (NDST + 7) / 8;

    for (int l = 0; l < NLAYER; l++) {
        const float* xinU = (l == 0) ? x_user : x1;
        const float* xinN = (l == 0) ? x_news : (x1 + (size_t)NU * CC);
        float* xout = (l == 0) ? x1 : (float*)d_out;
        size_t wl = (size_t)l * 10 * CC * CC;

        ProjArgs pa;
        pa.XU = xinU; pa.XN = xinN; pa.gridU = gridU;
        pa.W[0] = Wh + wl + 0 * CC * CC;  pa.bias[0] = bq + (l * 2 + 0) * CC;              pa.out[0] = qh;
        pa.W[1] = Wh + wl + 2 * CC * CC;  pa.bias[1] = beff + ((l * 3 + 0) * 2 + 0) * CC;  pa.out[1] = krelh;
        pa.W[2] = Wh + wl + 3 * CC * CC;  pa.bias[2] = beff + ((l * 3 + 0) * 2 + 1) * CC;  pa.out[2] = vrelh;
        pa.W[3] = Wh + wl + 6 * CC * CC;  pa.bias[3] = beff + ((l * 3 + 2) * 2 + 0) * CC;  pa.out[3] = krelh + (size_t)(NU + NN) * CC;
        pa.W[4] = Wh + wl + 7 * CC * CC;  pa.bias[4] = beff + ((l * 3 + 2) * 2 + 1) * CC;  pa.out[4] = vrelh + (size_t)(NU + NN) * CC;
        pa.W[5] = Wh + wl + 1 * CC * CC;  pa.bias[5] = bq + (l * 2 + 1) * CC;              pa.out[5] = qh + (size_t)NU * CC;
        pa.W[6] = Wh + wl + 4 * CC * CC;  pa.bias[6] = beff + ((l * 3 + 1) * 2 + 0) * CC;  pa.out[6] = krelh + (size_t)NU * CC;
        pa.W[7] = Wh + wl + 5 * CC * CC;  pa.bias[7] = beff + ((l * 3 + 1) * 2 + 1) * CC;  pa.out[7] = vrelh + (size_t)NU * CC;
        proj_kernel<<<gridU + gridN, 256, smemProj, 0>>>(pa);

        agg_kernel<<<aggBlocks, 256, 0, 0>>>(offAll, srt, qh, krelh, vrelh,
                                             p_rel + l * 12, aggr);

        OutArgs oa;
        oa.gridU = gridU;
        oa.aggU1 = aggr + (size_t)NN * CC;
        oa.aggU2 = aggr + (size_t)(NN + NU) * CC;
        oa.aggN  = aggr;
        oa.WU = Wh + wl + 8 * CC * CC;  oa.WN = Wh + wl + 9 * CC * CC;
        oa.biasU = ba + (l * 2 + 0) * CC;  oa.biasN = ba + (l * 2 + 1) * CC;
        oa.YU = xout;  oa.YN = xout + (size_t)NU * CC;
        oa.xoldU = xinU;  oa.xoldN = xinN;
        oa.skipU = skip + l * 2 + 0;  oa.skipN = skip + l * 2 + 1;
        out_kernel<<<gridU + gridN, 256, smemOut, 0>>>(oa);
    }
}